// round 10
// baseline (speedup 1.0000x reference)
#include <cuda_runtime.h>
#include <cuda_fp16.h>
#include <cstdint>

// smem: W0,W1 = 32KB f16 weight tiles [k=128][n=128]; H,T1,T2 = 32KB f16 act tiles [128][128]
#define W0OFF 0
#define W1OFF 32768
#define HOFF  65536
#define T1OFF 98304
#define T2OFF 131072
#define SM_TOTAL 163840   // 160KB -> 1 CTA/SM, 16 warps

// pre-swizzled f16 weight tile images (exact smem layout), built once per launch
__device__ __align__(16) unsigned char g_wtiles[11][32768];

// f16 tile swizzle: [row][col] (128 cols), row stride 256B, 16B-chunk XOR
__device__ __forceinline__ uint32_t AS(int r, int c) {
    return (uint32_t)(r * 256 + (((c >> 3) ^ (r & 7)) << 4) + (c & 7) * 2);
}
__device__ __forceinline__ uint32_t s2u(const void* p) {
    uint32_t a;
    asm("{ .reg .u64 t; cvta.to.shared.u64 t, %1; cvt.u32.u64 %0, t; }" : "=r"(a) : "l"(p));
    return a;
}
__device__ __forceinline__ uint32_t pack2(float a, float b) {
    __half2 h = __floats2half2_rn(a, b);
    return *reinterpret_cast<uint32_t*>(&h);
}
__device__ __forceinline__ void sts32(uint32_t a, uint32_t v) {
    asm volatile("st.shared.b32 [%0], %1;" :: "r"(a), "r"(v));
}
__device__ __forceinline__ void sts64(uint32_t a, uint32_t x, uint32_t y) {
    asm volatile("st.shared.v2.b32 [%0], {%1,%2};" :: "r"(a), "r"(x), "r"(y));
}
__device__ __forceinline__ void ldsm4(uint32_t r[4], uint32_t a) {
    asm volatile("ldmatrix.sync.aligned.m8n8.x4.shared.b16 {%0,%1,%2,%3}, [%4];"
        : "=r"(r[0]), "=r"(r[1]), "=r"(r[2]), "=r"(r[3]) : "r"(a));
}
__device__ __forceinline__ void ldsm4t(uint32_t r[4], uint32_t a) {
    asm volatile("ldmatrix.sync.aligned.m8n8.x4.trans.shared.b16 {%0,%1,%2,%3}, [%4];"
        : "=r"(r[0]), "=r"(r[1]), "=r"(r[2]), "=r"(r[3]) : "r"(a));
}
__device__ __forceinline__ void ldsm2t(uint32_t r[2], uint32_t a) {
    asm volatile("ldmatrix.sync.aligned.m8n8.x2.trans.shared.b16 {%0,%1}, [%2];"
        : "=r"(r[0]), "=r"(r[1]) : "r"(a));
}
__device__ __forceinline__ void mma16(float c[4], const uint32_t a[4], uint32_t b0, uint32_t b1) {
    asm volatile("mma.sync.aligned.m16n8k16.row.col.f32.f16.f16.f32 "
        "{%0,%1,%2,%3}, {%4,%5,%6,%7}, {%8,%9}, {%0,%1,%2,%3};"
        : "+f"(c[0]), "+f"(c[1]), "+f"(c[2]), "+f"(c[3])
        : "r"(a[0]), "r"(a[1]), "r"(a[2]), "r"(a[3]), "r"(b0), "r"(b1));
}
template<int NF>
__device__ __forceinline__ void zacc(float a[2][NF][4]) {
#pragma unroll
    for (int i = 0; i < 2; ++i)
#pragma unroll
        for (int j = 0; j < NF; ++j)
#pragma unroll
            for (int k = 0; k < 4; ++k) a[i][j][k] = 0.f;
}

// ---- async weight tile copy: linear 32KB over 512 threads, 4 x 16B each ----
__device__ __forceinline__ void wcopy(uint32_t dstS, int m, int tid) {
#pragma unroll
    for (int i = 0; i < 4; ++i) {
        uint32_t off = (uint32_t)(tid + 512 * i) * 16u;
        asm volatile("{ .reg .u64 gp; cvta.to.global.u64 gp, %1;\n\t"
                     "cp.async.cg.shared.global [%0], [gp], 16; }"
                     :: "r"(dstS + off), "l"(g_wtiles[m] + off));
    }
}
#define CP_WAIT() asm volatile("cp.async.wait_all;" ::: "memory")

// ---- GEMM: C[128x128] (+)= A[128x128] * W, W tile [k][n] via ldsm.trans ----
// warp grid: m-group = w&3 (32 rows), n-group = w>>2 (32 cols)
__device__ __forceinline__ void gemm_w8(float acc[2][4][4], uint32_t At, uint32_t Wt,
                                        int w, int lane) {
    const int arow = (w & 3) * 32 + ((lane >> 3) & 1) * 8 + (lane & 7);
    const uint32_t abase = At + (uint32_t)arow * 256u;
    const uint32_t ax = (uint32_t)(arow & 7);
    const uint32_t atc = (uint32_t)((lane >> 4) & 1);
    const int kro = ((lane >> 4) & 1) * 8 + (lane & 7);
    const uint32_t kx = (uint32_t)(lane & 7);
    const uint32_t nch = 4u * (uint32_t)(w >> 2) + (uint32_t)((lane >> 3) & 1);
    const uint32_t bbase = Wt + (uint32_t)kro * 256u;
    const uint32_t bo0 = ((nch ^ kx) << 4), bo1 = (((nch + 2u) ^ kx) << 4);
#pragma unroll
    for (int s = 0; s < 8; ++s) {
        uint32_t ao = (((2u * (uint32_t)s + atc) ^ ax) << 4);
        uint32_t a0[4], a1[4], p[4], q[4];
        ldsm4(a0, abase + ao);
        ldsm4(a1, abase + 4096u + ao);
        ldsm4t(p, bbase + (uint32_t)s * 4096u + bo0);
        ldsm4t(q, bbase + (uint32_t)s * 4096u + bo1);
        mma16(acc[0][0], a0, p[0], p[2]); mma16(acc[1][0], a1, p[0], p[2]);
        mma16(acc[0][1], a0, p[1], p[3]); mma16(acc[1][1], a1, p[1], p[3]);
        mma16(acc[0][2], a0, q[0], q[2]); mma16(acc[1][2], a1, q[0], q[2]);
        mma16(acc[0][3], a0, q[1], q[3]); mma16(acc[1][3], a1, q[1], q[3]);
    }
}

// ---- fused dual GEMM (K and Q projections share A) ----
__device__ __forceinline__ void gemm_kq(float aK[2][4][4], float aQ[2][4][4],
                                        uint32_t At, uint32_t B0, uint32_t B1,
                                        int w, int lane) {
    const int arow = (w & 3) * 32 + ((lane >> 3) & 1) * 8 + (lane & 7);
    const uint32_t abase = At + (uint32_t)arow * 256u;
    const uint32_t ax = (uint32_t)(arow & 7);
    const uint32_t atc = (uint32_t)((lane >> 4) & 1);
    const int kro = ((lane >> 4) & 1) * 8 + (lane & 7);
    const uint32_t kx = (uint32_t)(lane & 7);
    const uint32_t nch = 4u * (uint32_t)(w >> 2) + (uint32_t)((lane >> 3) & 1);
    const uint32_t bb0 = B0 + (uint32_t)kro * 256u;
    const uint32_t bb1 = B1 + (uint32_t)kro * 256u;
    const uint32_t bo0 = ((nch ^ kx) << 4), bo1 = (((nch + 2u) ^ kx) << 4);
#pragma unroll
    for (int s = 0; s < 8; ++s) {
        uint32_t ao = (((2u * (uint32_t)s + atc) ^ ax) << 4);
        uint32_t a0[4], a1[4], p[4], q[4], r[4], t[4];
        ldsm4(a0, abase + ao);
        ldsm4(a1, abase + 4096u + ao);
        ldsm4t(p, bb0 + (uint32_t)s * 4096u + bo0);
        ldsm4t(q, bb0 + (uint32_t)s * 4096u + bo1);
        ldsm4t(r, bb1 + (uint32_t)s * 4096u + bo0);
        ldsm4t(t, bb1 + (uint32_t)s * 4096u + bo1);
        mma16(aK[0][0], a0, p[0], p[2]); mma16(aK[1][0], a1, p[0], p[2]);
        mma16(aK[0][1], a0, p[1], p[3]); mma16(aK[1][1], a1, p[1], p[3]);
        mma16(aK[0][2], a0, q[0], q[2]); mma16(aK[1][2], a1, q[0], q[2]);
        mma16(aK[0][3], a0, q[1], q[3]); mma16(aK[1][3], a1, q[1], q[3]);
        mma16(aQ[0][0], a0, r[0], r[2]); mma16(aQ[1][0], a1, r[0], r[2]);
        mma16(aQ[0][1], a0, r[1], r[3]); mma16(aQ[1][1], a1, r[1], r[3]);
        mma16(aQ[0][2], a0, t[0], t[2]); mma16(aQ[1][2], a1, t[0], t[2]);
        mma16(aQ[0][3], a0, t[1], t[3]); mma16(aQ[1][3], a1, t[1], t[3]);
    }
}

// ---- epilogue: fp32 acc -> f16 act tile ----
__device__ __forceinline__ void epi4(uint32_t dst, float acc[2][4][4], const float* bias,
                                     bool relu, int w, int lane) {
    const int r0 = (w & 3) * 32 + (lane >> 2);
    const int c0 = (w >> 2) * 32 + 2 * (lane & 3);
#pragma unroll
    for (int nf = 0; nf < 4; ++nf) {
        int col = c0 + 8 * nf;
        float b0 = bias ? __ldg(bias + col)     : 0.f;
        float b1 = bias ? __ldg(bias + col + 1) : 0.f;
#pragma unroll
        for (int mi = 0; mi < 2; ++mi)
#pragma unroll
            for (int hh = 0; hh < 2; ++hh) {
                int r = r0 + 16 * mi + 8 * hh;
                float v0 = acc[mi][nf][2 * hh + 0] + b0;
                float v1 = acc[mi][nf][2 * hh + 1] + b1;
                if (relu) { v0 = fmaxf(v0, 0.f); v1 = fmaxf(v1, 0.f); }
                sts32(dst + AS(r, col), pack2(v0, v1));
            }
    }
}

// ---- scores (diag) + in-register softmax + P->T2 (warps 0..7 only) ----
__device__ __forceinline__ void scores_softmax(uint32_t Qt, uint32_t Kt,
                                               const float* mask, int b0, int w, int lane) {
    const int g = w >> 1;   // batch 0..3
    const int gid = lane >> 2, ctig = lane & 3;
    const int arow = 16 * w + ((lane >> 3) & 1) * 8 + (lane & 7);
    const uint32_t abase = Qt + (uint32_t)arow * 256u;
    const uint32_t x7 = (uint32_t)(lane & 7);
    const uint32_t atc = (uint32_t)((lane >> 4) & 1);
    const int brow = 32 * g + ((lane >> 3) & 1) * 8 + (lane & 7);
    const uint32_t bb0 = Kt + (uint32_t)brow * 256u;
    const uint32_t bb1 = bb0 + 4096u;
    float aS[4][4];
#pragma unroll
    for (int j = 0; j < 4; ++j)
#pragma unroll
        for (int k = 0; k < 4; ++k) aS[j][k] = 0.f;
#pragma unroll
    for (int s = 0; s < 8; ++s) {
        uint32_t ao = (((2u * (uint32_t)s + atc) ^ x7) << 4);
        uint32_t qa[4], k0[4], k1[4];
        ldsm4(qa, abase + ao);
        ldsm4(k0, bb0 + ao);
        ldsm4(k1, bb1 + ao);
        mma16(aS[0], qa, k0[0], k0[2]);
        mma16(aS[1], qa, k0[1], k0[3]);
        mma16(aS[2], qa, k1[0], k1[2]);
        mma16(aS[3], qa, k1[1], k1[3]);
    }
    const float* mA = mask + (((size_t)(b0 + g)) * 32 + (16 * (w & 1) + gid)) * 32;
    const float* mB = mA + 8 * 32;
    float lA[8], lB[8];
#pragma unroll
    for (int nf = 0; nf < 4; ++nf)
#pragma unroll
        for (int e = 0; e < 2; ++e) {
            int cl = 8 * nf + 2 * ctig + e;
            float ma = __ldg(mA + cl), mb = __ldg(mB + cl);
            lA[2 * nf + e] = aS[nf][e]     * ma - 9e15f * (1.0f - ma);
            lB[2 * nf + e] = aS[nf][2 + e] * mb - 9e15f * (1.0f - mb);
        }
    float mxA = lA[0], mxB = lB[0];
#pragma unroll
    for (int j = 1; j < 8; ++j) { mxA = fmaxf(mxA, lA[j]); mxB = fmaxf(mxB, lB[j]); }
    mxA = fmaxf(mxA, __shfl_xor_sync(0xffffffffu, mxA, 1));
    mxA = fmaxf(mxA, __shfl_xor_sync(0xffffffffu, mxA, 2));
    mxB = fmaxf(mxB, __shfl_xor_sync(0xffffffffu, mxB, 1));
    mxB = fmaxf(mxB, __shfl_xor_sync(0xffffffffu, mxB, 2));
    float sA = 0.f, sB = 0.f;
#pragma unroll
    for (int j = 0; j < 8; ++j) {
        lA[j] = __expf(lA[j] - mxA); sA += lA[j];
        lB[j] = __expf(lB[j] - mxB); sB += lB[j];
    }
    sA += __shfl_xor_sync(0xffffffffu, sA, 1);
    sA += __shfl_xor_sync(0xffffffffu, sA, 2);
    sB += __shfl_xor_sync(0xffffffffu, sB, 1);
    sB += __shfl_xor_sync(0xffffffffu, sB, 2);
    float iA = 1.0f / sA, iB = 1.0f / sB;
    const int rA = 16 * w + gid;
#pragma unroll
    for (int nf = 0; nf < 4; ++nf) {
        int col = 32 * g + 8 * nf + 2 * ctig;
        sts32(Qt + AS(rA,     col), pack2(lA[2 * nf] * iA, lA[2 * nf + 1] * iA));
        sts32(Qt + AS(rA + 8, col), pack2(lB[2 * nf] * iB, lB[2 * nf + 1] * iB));
    }
}

// ---- PV (diag, K=32): A = P (T2, own batch k-cols), B = V (H) via trans ----
__device__ __forceinline__ void gemm_pv(float acc[2][4][4], uint32_t Pt, uint32_t Vt,
                                        int w, int lane) {
    const int b = w & 3;
    const int arow = 32 * b + ((lane >> 3) & 1) * 8 + (lane & 7);
    const uint32_t abase = Pt + (uint32_t)arow * 256u;
    const uint32_t ax = (uint32_t)(arow & 7);
    const uint32_t atc = (uint32_t)((lane >> 4) & 1);
    const int kro = ((lane >> 4) & 1) * 8 + (lane & 7);
    const uint32_t kx = (uint32_t)(lane & 7);
    const uint32_t nch = 4u * (uint32_t)(w >> 2) + (uint32_t)((lane >> 3) & 1);
    const uint32_t bbase = Vt + (uint32_t)(32 * b + kro) * 256u;
    const uint32_t bo0 = ((nch ^ kx) << 4), bo1 = (((nch + 2u) ^ kx) << 4);
#pragma unroll
    for (int s = 0; s < 2; ++s) {
        uint32_t ach = 4u * (uint32_t)b + 2u * (uint32_t)s + atc;
        uint32_t ao = ((ach ^ ax) << 4);
        uint32_t a0[4], a1[4], p[4], q[4];
        ldsm4(a0, abase + ao);
        ldsm4(a1, abase + 4096u + ao);
        ldsm4t(p, bbase + (uint32_t)s * 4096u + bo0);
        ldsm4t(q, bbase + (uint32_t)s * 4096u + bo1);
        mma16(acc[0][0], a0, p[0], p[2]); mma16(acc[1][0], a1, p[0], p[2]);
        mma16(acc[0][1], a0, p[1], p[3]); mma16(acc[1][1], a1, p[1], p[3]);
        mma16(acc[0][2], a0, q[0], q[2]); mma16(acc[1][2], a1, q[0], q[2]);
        mma16(acc[0][3], a0, q[1], q[3]); mma16(acc[1][3], a1, q[1], q[3]);
    }
}

__device__ __forceinline__ void att_block(
    uint32_t H, uint32_t T1, uint32_t T2, uint32_t W0, uint32_t W1,
    const float* kb, const float* qb, const float* vb, const float* ob,
    const float* mask, int b0, int mv, int mo, int mn1, int mn2,
    int w, int lane, int tid)
{
    {   // K, Q projections (fused)
        float aK[2][4][4], aQ[2][4][4];
        zacc<4>(aK); zacc<4>(aQ);
        gemm_kq(aK, aQ, H, W0, W1, w, lane);
        __syncthreads();
        wcopy(W0, mv, tid);
        wcopy(W1, mo, tid);
        epi4(T1, aK, kb, true, w, lane);   // K -> T1 [j][h]
        epi4(T2, aQ, qb, true, w, lane);   // Q -> T2 [i][h]
        CP_WAIT();
        __syncthreads();
    }
    {   // V projection; scores+softmax on warps 0-7 (P overwrites own Q rows in T2)
        float aV[2][4][4];
        zacc<4>(aV);
        gemm_w8(aV, H, W0, w, lane);
        __syncthreads();
        if (mn1 >= 0) wcopy(W0, mn1, tid);
        epi4(H, aV, vb, true, w, lane);    // V -> H [j][h]
        if (w < 8) scores_softmax(T2, T1, mask, b0, w, lane);
        CP_WAIT();
        __syncthreads();
    }
    {   // PV (diag) -> T1
        float aP[2][4][4];
        zacc<4>(aP);
        gemm_pv(aP, T2, H, w, lane);
        __syncthreads();
        epi4(T1, aP, nullptr, false, w, lane);
        __syncthreads();
    }
    {   // out projection -> H
        float aO[2][4][4];
        zacc<4>(aO);
        gemm_w8(aO, T1, W1, w, lane);
        __syncthreads();
        if (mn2 >= 0) wcopy(W1, mn2, tid);
        epi4(H, aO, ob, true, w, lane);
        CP_WAIT();
        __syncthreads();
    }
}

__global__ void __launch_bounds__(512, 1)
dgn_f16(const float* __restrict__ x, const float* __restrict__ mask,
        const float* __restrict__ enc_b,
        const float* __restrict__ a1_vb, const float* __restrict__ a1_kb,
        const float* __restrict__ a1_qb, const float* __restrict__ a1_ob,
        const float* __restrict__ a2_vb, const float* __restrict__ a2_kb,
        const float* __restrict__ a2_qb, const float* __restrict__ a2_ob,
        const float* __restrict__ qhb,
        float* __restrict__ out)
{
    extern __shared__ __align__(16) char sm[];
    const uint32_t base = s2u(sm);
    const uint32_t W0 = base + W0OFF, W1 = base + W1OFF;
    const uint32_t H = base + HOFF, T1 = base + T1OFF, T2 = base + T2OFF;
    const int tid = threadIdx.x, w = tid >> 5, lane = tid & 31;
    const int b0 = blockIdx.x * 4;

    wcopy(W0, 0, tid);
    wcopy(W1, 1, tid);
    // x (f32 [128][256]) -> f16 tiles T1 (cols 0-127), T2 (cols 128-255)
#pragma unroll
    for (int it = 0; it < 16; ++it) {
        int idx = tid + 512 * it;          // 0..8191
        int r = idx >> 6, c4 = idx & 63;
        int col = 4 * c4;
        float4 v = *reinterpret_cast<const float4*>(
            x + (((size_t)b0 + (r >> 5)) * 32 + (r & 31)) * 256 + col);
        uint32_t dst = (col < 128 ? T1 : T2) + AS(r, col & 127);
        sts64(dst, pack2(v.x, v.y), pack2(v.z, v.w));
    }
    CP_WAIT();
    __syncthreads();

    // encoder (K=256): two accumulating passes
    {
        float aE[2][4][4];
        zacc<4>(aE);
        gemm_w8(aE, T1, W0, w, lane);
        gemm_w8(aE, T2, W1, w, lane);
        __syncthreads();
        wcopy(W0, 2, tid);
        wcopy(W1, 3, tid);
        epi4(H, aE, enc_b, true, w, lane);
        CP_WAIT();
        __syncthreads();
    }

    att_block(H, T1, T2, W0, W1, a1_kb, a1_qb, a1_vb, a1_ob,
              mask, b0, 4, 5, 6, 7, w, lane, tid);
    att_block(H, T1, T2, W0, W1, a2_kb, a2_qb, a2_vb, a2_ob,
              mask, b0, 8, 9, 10, -1, w, lane, tid);

    // head: N=32, 16 warps (m-group w&3, n8-slice w>>2); B = W0 (tile 10) via ldsm x2 trans
    {
        const int arow = (w & 3) * 32 + ((lane >> 3) & 1) * 8 + (lane & 7);
        const uint32_t abase = H + (uint32_t)arow * 256u;
        const uint32_t ax = (uint32_t)(arow & 7);
        const uint32_t atc = (uint32_t)((lane >> 4) & 1);
        const int kro2 = ((lane >> 3) & 1) * 8 + (lane & 7);
        const uint32_t bb = W0 + (uint32_t)kro2 * 256u;
        const uint32_t boH = (((uint32_t)(w >> 2) ^ (uint32_t)(lane & 7)) << 4);
        float acc[2][4];
#pragma unroll
        for (int i = 0; i < 2; ++i)
#pragma unroll
            for (int k = 0; k < 4; ++k) acc[i][k] = 0.f;
#pragma unroll
        for (int s = 0; s < 8; ++s) {
            uint32_t ao = (((2u * (uint32_t)s + atc) ^ ax) << 4);
            uint32_t a0[4], a1[4], b[2];
            ldsm4(a0, abase + ao);
            ldsm4(a1, abase + 4096u + ao);
            ldsm2t(b, bb + (uint32_t)s * 4096u + boH);
            mma16(acc[0], a0, b[0], b[1]);
            mma16(acc[1], a1, b[0], b[1]);
        }
        const int r0 = (w & 3) * 32 + (lane >> 2);
        const int col = (w >> 2) * 8 + 2 * (lane & 3);
        float bb0 = __ldg(qhb + col), bb1 = __ldg(qhb + col + 1);
#pragma unroll
        for (int mi = 0; mi < 2; ++mi)
#pragma unroll
            for (int hh = 0; hh < 2; ++hh) {
                int r = r0 + 16 * mi + 8 * hh;
                float2 v = make_float2(acc[mi][2 * hh] + bb0, acc[mi][2 * hh + 1] + bb1);
                *reinterpret_cast<float2*>(
                    out + (((size_t)b0 + (r >> 5)) * 32 + (r & 31)) * 32 + col) = v;
            }
    }
}

// ---- prep: bake f32 weights into pre-swizzled f16 tile images ----
__global__ void wprep(const float* __restrict__ enc_w,
                      const float* __restrict__ k1, const float* __restrict__ q1,
                      const float* __restrict__ v1, const float* __restrict__ o1,
                      const float* __restrict__ k2, const float* __restrict__ q2,
                      const float* __restrict__ v2, const float* __restrict__ o2,
                      const float* __restrict__ hw)
{
    const int m = blockIdx.x, tid = threadIdx.x, w = tid >> 5, lane = tid & 31;
    unsigned char* dst = g_wtiles[m];
    const float* srcs[11] = { enc_w, enc_w + 128 * 128, k1, q1, v1, o1, k2, q2, v2, o2, hw };
    const float* src = srcs[m];
    if (m < 10) {
#pragma unroll
        for (int i = 0; i < 16; ++i) {
            int k = 16 * w + i;
            float4 v = __ldg(reinterpret_cast<const float4*>(src + (size_t)k * 128) + lane);
            int n = 4 * lane;
            uint32_t off = (uint32_t)k * 256u + ((((uint32_t)(n >> 3)) ^ (uint32_t)(k & 7)) << 4)
                           + (uint32_t)((n >> 2) & 1) * 8u;
            uint2 val = make_uint2(pack2(v.x, v.y), pack2(v.z, v.w));
            *reinterpret_cast<uint2*>(dst + off) = val;
        }
    } else {
        for (int i = tid; i < 2048; i += 256)
            reinterpret_cast<uint4*>(dst)[i] = make_uint4(0, 0, 0, 0);
        __syncthreads();
#pragma unroll
        for (int it = 0; it < 4; ++it) {
            int k = 16 * w + 4 * it + (lane >> 3);
            int n = 4 * (lane & 7);
            float4 v = __ldg(reinterpret_cast<const float4*>(src + (size_t)k * 32) + (lane & 7));
            uint32_t off = (uint32_t)k * 256u + ((((uint32_t)(n >> 3)) ^ (uint32_t)(k & 7)) << 4)
                           + (uint32_t)((n >> 2) & 1) * 8u;
            uint2 val = make_uint2(pack2(v.x, v.y), pack2(v.z, v.w));
            *reinterpret_cast<uint2*>(dst + off) = val;
        }
    }
}

extern "C" void kernel_launch(void* const* d_in, const int* in_sizes, int n_in,
                              void* d_out, int out_size)
{
    const float* x     = (const float*)d_in[0];
    const float* mask  = (const float*)d_in[1];
    const float* enc_w = (const float*)d_in[2];
    const float* enc_b = (const float*)d_in[3];
    const float* a1_vw = (const float*)d_in[4];
    const float* a1_vb = (const float*)d_in[5];
    const float* a1_kw = (const float*)d_in[6];
    const float* a1_kb = (const float*)d_in[7];
    const float* a1_qw = (const float*)d_in[8];
    const float* a1_qb = (const float*)d_in[9];
    const float* a1_ow = (const float*)d_in[10];
    const float* a1_ob = (const float*)d_in[11];
    const float* a2_vw = (const float*)d_in[12];
    const float* a2_vb = (const float*)d_in[13];
    const float* a2_kw = (const float*)d_in[14];
    const float* a2_kb = (const float*)d_in[15];
    const float* a2_qw = (const float*)d_in[16];
    const float* a2_qb = (const float*)d_in[17];
    const float* a2_ow = (const float*)d_in[18];
    const float* a2_ob = (const float*)d_in[19];
    const float* q_w   = (const float*)d_in[20];
    const float* q_b   = (const float*)d_in[21];

    wprep<<<11, 256>>>(enc_w, a1_kw, a1_qw, a1_vw, a1_ow,
                       a2_kw, a2_qw, a2_vw, a2_ow, q_w);

    cudaFuncSetAttribute(dgn_f16, cudaFuncAttributeMaxDynamicSharedMemorySize, SM_TOTAL);
    dgn_f16<<<1024, 512, SM_TOTAL>>>(
        x, mask, enc_b,
        a1_vb, a1_kb, a1_qb, a1_ob,
        a2_vb, a2_kb, a2_qb, a2_ob,
        q_b, (float*)d_out);
}

// round 11
// speedup vs baseline: 1.5820x; 1.5820x over previous
#include <cuda_runtime.h>
#include <cuda_fp16.h>
#include <cstdint>

// smem (bytes): W0,W1 = 32KB f16 weight tiles [k=128][n=128]; H,T1,T2 = 16KB f16 act tiles [64][128]
#define W0OFF 0
#define W1OFF 32768
#define HOFF  65536
#define T1OFF 81920
#define T2OFF 98304
#define SM_TOTAL 114688   // 112KB -> 2 CTAs/SM

// pre-swizzled f16 weight tile images (exact smem layout), built once per launch
__device__ __align__(16) unsigned char g_wtiles[11][32768];

// f16 tile swizzle: [row][col] (128 cols), row stride 256B, 16B-chunk XOR
__device__ __forceinline__ uint32_t AS(int r, int c) {
    return (uint32_t)(r * 256 + (((c >> 3) ^ (r & 7)) << 4) + (c & 7) * 2);
}
__device__ __forceinline__ uint32_t s2u(const void* p) {
    uint32_t a;
    asm("{ .reg .u64 t; cvta.to.shared.u64 t, %1; cvt.u32.u64 %0, t; }" : "=r"(a) : "l"(p));
    return a;
}
__device__ __forceinline__ uint32_t pack2(float a, float b) {
    __half2 h = __floats2half2_rn(a, b);
    return *reinterpret_cast<uint32_t*>(&h);
}
__device__ __forceinline__ void sts32(uint32_t a, uint32_t v) {
    asm volatile("st.shared.b32 [%0], %1;" :: "r"(a), "r"(v));
}
__device__ __forceinline__ void sts64(uint32_t a, uint32_t x, uint32_t y) {
    asm volatile("st.shared.v2.b32 [%0], {%1,%2};" :: "r"(a), "r"(x), "r"(y));
}
__device__ __forceinline__ void ldsm4(uint32_t r[4], uint32_t a) {
    asm volatile("ldmatrix.sync.aligned.m8n8.x4.shared.b16 {%0,%1,%2,%3}, [%4];"
        : "=r"(r[0]), "=r"(r[1]), "=r"(r[2]), "=r"(r[3]) : "r"(a));
}
__device__ __forceinline__ void ldsm4t(uint32_t r[4], uint32_t a) {
    asm volatile("ldmatrix.sync.aligned.m8n8.x4.trans.shared.b16 {%0,%1,%2,%3}, [%4];"
        : "=r"(r[0]), "=r"(r[1]), "=r"(r[2]), "=r"(r[3]) : "r"(a));
}
__device__ __forceinline__ void ldsm2t(uint32_t r[2], uint32_t a) {
    asm volatile("ldmatrix.sync.aligned.m8n8.x2.trans.shared.b16 {%0,%1}, [%2];"
        : "=r"(r[0]), "=r"(r[1]) : "r"(a));
}
__device__ __forceinline__ void mma16(float c[4], const uint32_t a[4], uint32_t b0, uint32_t b1) {
    asm volatile("mma.sync.aligned.m16n8k16.row.col.f32.f16.f16.f32 "
        "{%0,%1,%2,%3}, {%4,%5,%6,%7}, {%8,%9}, {%0,%1,%2,%3};"
        : "+f"(c[0]), "+f"(c[1]), "+f"(c[2]), "+f"(c[3])
        : "r"(a[0]), "r"(a[1]), "r"(a[2]), "r"(a[3]), "r"(b0), "r"(b1));
}
template<int NF>
__device__ __forceinline__ void zacc(float a[2][NF][4]) {
#pragma unroll
    for (int i = 0; i < 2; ++i)
#pragma unroll
        for (int j = 0; j < NF; ++j)
#pragma unroll
            for (int k = 0; k < 4; ++k) a[i][j][k] = 0.f;
}

// ---- async weight tile copy: linear 32KB, 8 x 16B per thread ----
__device__ __forceinline__ void wcopy(uint32_t dstS, int m, int tid) {
#pragma unroll
    for (int i = 0; i < 8; ++i) {
        uint32_t off = (uint32_t)(tid + 256 * i) * 16u;
        asm volatile("{ .reg .u64 gp; cvta.to.global.u64 gp, %1;\n\t"
                     "cp.async.cg.shared.global [%0], [gp], 16; }"
                     :: "r"(dstS + off), "l"(g_wtiles[m] + off));
    }
}
#define CP_WAIT() asm volatile("cp.async.wait_all;" ::: "memory")

// ---- GEMM: C[64x128] (+)= A[64x128] * W, A act tile, W weight tile [k][n] via ldsm.trans ----
__device__ __forceinline__ void gemm_w8(float acc[2][4][4], uint32_t At, uint32_t Wt,
                                        int w, int lane) {
    const int arow = (w & 1) * 32 + ((lane >> 3) & 1) * 8 + (lane & 7);
    const uint32_t abase = At + (uint32_t)arow * 256u;
    const uint32_t ax = (uint32_t)(arow & 7);
    const uint32_t atc = (uint32_t)((lane >> 4) & 1);
    const int kro = ((lane >> 4) & 1) * 8 + (lane & 7);
    const uint32_t kx = (uint32_t)(lane & 7);
    const uint32_t nch = 4u * (uint32_t)(w >> 1) + (uint32_t)((lane >> 3) & 1);
    const uint32_t bbase = Wt + (uint32_t)kro * 256u;
    const uint32_t bo0 = ((nch ^ kx) << 4), bo1 = (((nch + 2u) ^ kx) << 4);
#pragma unroll
    for (int s = 0; s < 8; ++s) {
        uint32_t ao = (((2u * (uint32_t)s + atc) ^ ax) << 4);
        uint32_t a0[4], a1[4], p[4], q[4];
        ldsm4(a0, abase + ao);
        ldsm4(a1, abase + 4096u + ao);
        ldsm4t(p, bbase + (uint32_t)s * 4096u + bo0);
        ldsm4t(q, bbase + (uint32_t)s * 4096u + bo1);
        mma16(acc[0][0], a0, p[0], p[2]); mma16(acc[1][0], a1, p[0], p[2]);
        mma16(acc[0][1], a0, p[1], p[3]); mma16(acc[1][1], a1, p[1], p[3]);
        mma16(acc[0][2], a0, q[0], q[2]); mma16(acc[1][2], a1, q[0], q[2]);
        mma16(acc[0][3], a0, q[1], q[3]); mma16(acc[1][3], a1, q[1], q[3]);
    }
}

// ---- fused dual GEMM (K and Q projections share A) ----
__device__ __forceinline__ void gemm_kq(float aK[2][4][4], float aQ[2][4][4],
                                        uint32_t At, uint32_t B0, uint32_t B1,
                                        int w, int lane) {
    const int arow = (w & 1) * 32 + ((lane >> 3) & 1) * 8 + (lane & 7);
    const uint32_t abase = At + (uint32_t)arow * 256u;
    const uint32_t ax = (uint32_t)(arow & 7);
    const uint32_t atc = (uint32_t)((lane >> 4) & 1);
    const int kro = ((lane >> 4) & 1) * 8 + (lane & 7);
    const uint32_t kx = (uint32_t)(lane & 7);
    const uint32_t nch = 4u * (uint32_t)(w >> 1) + (uint32_t)((lane >> 3) & 1);
    const uint32_t bb0 = B0 + (uint32_t)kro * 256u;
    const uint32_t bb1 = B1 + (uint32_t)kro * 256u;
    const uint32_t bo0 = ((nch ^ kx) << 4), bo1 = (((nch + 2u) ^ kx) << 4);
#pragma unroll
    for (int s = 0; s < 8; ++s) {
        uint32_t ao = (((2u * (uint32_t)s + atc) ^ ax) << 4);
        uint32_t a0[4], a1[4], p[4], q[4], r[4], t[4];
        ldsm4(a0, abase + ao);
        ldsm4(a1, abase + 4096u + ao);
        ldsm4t(p, bb0 + (uint32_t)s * 4096u + bo0);
        ldsm4t(q, bb0 + (uint32_t)s * 4096u + bo1);
        ldsm4t(r, bb1 + (uint32_t)s * 4096u + bo0);
        ldsm4t(t, bb1 + (uint32_t)s * 4096u + bo1);
        mma16(aK[0][0], a0, p[0], p[2]); mma16(aK[1][0], a1, p[0], p[2]);
        mma16(aK[0][1], a0, p[1], p[3]); mma16(aK[1][1], a1, p[1], p[3]);
        mma16(aK[0][2], a0, q[0], q[2]); mma16(aK[1][2], a1, q[0], q[2]);
        mma16(aK[0][3], a0, q[1], q[3]); mma16(aK[1][3], a1, q[1], q[3]);
        mma16(aQ[0][0], a0, r[0], r[2]); mma16(aQ[1][0], a1, r[0], r[2]);
        mma16(aQ[0][1], a0, r[1], r[3]); mma16(aQ[1][1], a1, r[1], r[3]);
        mma16(aQ[0][2], a0, t[0], t[2]); mma16(aQ[1][2], a1, t[0], t[2]);
        mma16(aQ[0][3], a0, t[1], t[3]); mma16(aQ[1][3], a1, t[1], t[3]);
    }
}

// ---- epilogue: fp32 acc -> f16 act tile ----
__device__ __forceinline__ void epi4(uint32_t dst, float acc[2][4][4], const float* bias,
                                     bool relu, int w, int lane) {
    const int r0 = (w & 1) * 32 + (lane >> 2);
    const int c0 = (w >> 1) * 32 + 2 * (lane & 3);
#pragma unroll
    for (int nf = 0; nf < 4; ++nf) {
        int col = c0 + 8 * nf;
        float b0 = bias ? __ldg(bias + col)     : 0.f;
        float b1 = bias ? __ldg(bias + col + 1) : 0.f;
#pragma unroll
        for (int mi = 0; mi < 2; ++mi)
#pragma unroll
            for (int hh = 0; hh < 2; ++hh) {
                int r = r0 + 16 * mi + 8 * hh;
                float v0 = acc[mi][nf][2 * hh + 0] + b0;
                float v1 = acc[mi][nf][2 * hh + 1] + b1;
                if (relu) { v0 = fmaxf(v0, 0.f); v1 = fmaxf(v1, 0.f); }
                sts32(dst + AS(r, col), pack2(v0, v1));
            }
    }
}

// ---- scores (diag) + in-register softmax + P->T2 (warps 0..3 only) ----
__device__ __forceinline__ void scores_softmax(uint32_t Qt, uint32_t Kt,
                                               const float* mask, int b0, int w, int lane) {
    const int g = w >> 1;
    const int gid = lane >> 2, ctig = lane & 3;
    const int arow = 16 * w + ((lane >> 3) & 1) * 8 + (lane & 7);
    const uint32_t abase = Qt + (uint32_t)arow * 256u;
    const uint32_t x7 = (uint32_t)(lane & 7);
    const uint32_t atc = (uint32_t)((lane >> 4) & 1);
    const int brow = 32 * g + ((lane >> 3) & 1) * 8 + (lane & 7);
    const uint32_t bb0 = Kt + (uint32_t)brow * 256u;
    const uint32_t bb1 = bb0 + 4096u;
    float aS[4][4];
#pragma unroll
    for (int j = 0; j < 4; ++j)
#pragma unroll
        for (int k = 0; k < 4; ++k) aS[j][k] = 0.f;
#pragma unroll
    for (int s = 0; s < 8; ++s) {
        uint32_t ao = (((2u * (uint32_t)s + atc) ^ x7) << 4);
        uint32_t qa[4], k0[4], k1[4];
        ldsm4(qa, abase + ao);
        ldsm4(k0, bb0 + ao);
        ldsm4(k1, bb1 + ao);
        mma16(aS[0], qa, k0[0], k0[2]);
        mma16(aS[1], qa, k0[1], k0[3]);
        mma16(aS[2], qa, k1[0], k1[2]);
        mma16(aS[3], qa, k1[1], k1[3]);
    }
    const float* mA = mask + (((size_t)(b0 + g)) * 32 + (16 * (w & 1) + gid)) * 32;
    const float* mB = mA + 8 * 32;
    float lA[8], lB[8];
#pragma unroll
    for (int nf = 0; nf < 4; ++nf)
#pragma unroll
        for (int e = 0; e < 2; ++e) {
            int cl = 8 * nf + 2 * ctig + e;
            float ma = __ldg(mA + cl), mb = __ldg(mB + cl);
            lA[2 * nf + e] = aS[nf][e]     * ma - 9e15f * (1.0f - ma);
            lB[2 * nf + e] = aS[nf][2 + e] * mb - 9e15f * (1.0f - mb);
        }
    float mxA = lA[0], mxB = lB[0];
#pragma unroll
    for (int j = 1; j < 8; ++j) { mxA = fmaxf(mxA, lA[j]); mxB = fmaxf(mxB, lB[j]); }
    mxA = fmaxf(mxA, __shfl_xor_sync(0xffffffffu, mxA, 1));
    mxA = fmaxf(mxA, __shfl_xor_sync(0xffffffffu, mxA, 2));
    mxB = fmaxf(mxB, __shfl_xor_sync(0xffffffffu, mxB, 1));
    mxB = fmaxf(mxB, __shfl_xor_sync(0xffffffffu, mxB, 2));
    float sA = 0.f, sB = 0.f;
#pragma unroll
    for (int j = 0; j < 8; ++j) {
        lA[j] = __expf(lA[j] - mxA); sA += lA[j];
        lB[j] = __expf(lB[j] - mxB); sB += lB[j];
    }
    sA += __shfl_xor_sync(0xffffffffu, sA, 1);
    sA += __shfl_xor_sync(0xffffffffu, sA, 2);
    sB += __shfl_xor_sync(0xffffffffu, sB, 1);
    sB += __shfl_xor_sync(0xffffffffu, sB, 2);
    float iA = 1.0f / sA, iB = 1.0f / sB;
    const int rA = 16 * w + gid;
#pragma unroll
    for (int nf = 0; nf < 4; ++nf) {
        int col = 32 * g + 8 * nf + 2 * ctig;
        sts32(Qt + AS(rA,     col), pack2(lA[2 * nf] * iA, lA[2 * nf + 1] * iA));
        sts32(Qt + AS(rA + 8, col), pack2(lB[2 * nf] * iB, lB[2 * nf + 1] * iB));
    }
}

// ---- PV (diag, K=32): A = P (T2), B = V (H) via trans ----
__device__ __forceinline__ void gemm_pv(float acc[2][4][4], uint32_t Pt, uint32_t Vt,
                                        int w, int lane) {
    const int b = w & 1;
    const int arow = 32 * b + ((lane >> 3) & 1) * 8 + (lane & 7);
    const uint32_t abase = Pt + (uint32_t)arow * 256u;
    const uint32_t ax = (uint32_t)(arow & 7);
    const uint32_t atc = (uint32_t)((lane >> 4) & 1);
    const int kro = ((lane >> 4) & 1) * 8 + (lane & 7);
    const uint32_t kx = (uint32_t)(lane & 7);
    const uint32_t nch = 4u * (uint32_t)(w >> 1) + (uint32_t)((lane >> 3) & 1);
    const uint32_t bbase = Vt + (uint32_t)(32 * b + kro) * 256u;
    const uint32_t bo0 = ((nch ^ kx) << 4), bo1 = (((nch + 2u) ^ kx) << 4);
#pragma unroll
    for (int s = 0; s < 2; ++s) {
        uint32_t ach = 4u * (uint32_t)b + 2u * (uint32_t)s + atc;
        uint32_t ao = ((ach ^ ax) << 4);
        uint32_t a0[4], a1[4], p[4], q[4];
        ldsm4(a0, abase + ao);
        ldsm4(a1, abase + 4096u + ao);
        ldsm4t(p, bbase + (uint32_t)s * 4096u + bo0);
        ldsm4t(q, bbase + (uint32_t)s * 4096u + bo1);
        mma16(acc[0][0], a0, p[0], p[2]); mma16(acc[1][0], a1, p[0], p[2]);
        mma16(acc[0][1], a0, p[1], p[3]); mma16(acc[1][1], a1, p[1], p[3]);
        mma16(acc[0][2], a0, q[0], q[2]); mma16(acc[1][2], a1, q[0], q[2]);
        mma16(acc[0][3], a0, q[1], q[3]); mma16(acc[1][3], a1, q[1], q[3]);
    }
}

template<bool LAST>
__device__ __forceinline__ void att_block(
    uint32_t H, uint32_t T1, uint32_t T2, uint32_t W0, uint32_t W1,
    const float* kb, const float* qb, const float* vb, const float* ob,
    const float* mask, int b0, int mv, int mo, int mn1,
    int w, int lane, int tid)
{
    {   // K, Q projections (fused)
        float aK[2][4][4], aQ[2][4][4];
        zacc<4>(aK); zacc<4>(aQ);
        gemm_kq(aK, aQ, H, W0, W1, w, lane);
        __syncthreads();                    // protect W0/W1 overwrite
        wcopy(W0, mv, tid);
        wcopy(W1, mo, tid);
        epi4(T1, aK, kb, true, w, lane);    // K -> T1 [j][h]
        epi4(T2, aQ, qb, true, w, lane);    // Q -> T2 [i][h]
        CP_WAIT();
        __syncthreads();
    }
    {   // V projection; scores+softmax on warps 0-3 (P overwrites own Q rows in T2)
        float aV[2][4][4];
        zacc<4>(aV);
        gemm_w8(aV, H, W0, w, lane);
        __syncthreads();                    // protect W0 overwrite + H write
        wcopy(W0, mn1, tid);
        epi4(H, aV, vb, true, w, lane);     // V -> H [j][h]
        if (w < 4) scores_softmax(T2, T1, mask, b0, w, lane);
        CP_WAIT();
        __syncthreads();
    }
    {   // PV (diag) -> T1. No internal barrier: gemm_pv reads T2,H; epi writes T1,
        // whose last readers (scores, prev phase) are behind the phase-2 barrier.
        float aP[2][4][4];
        zacc<4>(aP);
        gemm_pv(aP, T2, H, w, lane);
        epi4(T1, aP, nullptr, false, w, lane);
        __syncthreads();
    }
    {   // out projection -> H
        float aO[2][4][4];
        zacc<4>(aO);
        gemm_w8(aO, T1, W1, w, lane);
        if (!LAST) {
            __syncthreads();                // protect W1 overwrite
            wcopy(W1, 7, tid);              // a2 out-proj tile
            epi4(H, aO, ob, true, w, lane);
            CP_WAIT();
        } else {
            // no wcopy: epi writes H, whose last readers (gemm_pv) are behind
            // the phase-3 barrier -> no internal barrier needed
            epi4(H, aO, ob, true, w, lane);
        }
        __syncthreads();
    }
}

__global__ void __launch_bounds__(256, 2)
dgn_f16(const float* __restrict__ x, const float* __restrict__ mask,
        const float* __restrict__ enc_b,
        const float* __restrict__ a1_vb, const float* __restrict__ a1_kb,
        const float* __restrict__ a1_qb, const float* __restrict__ a1_ob,
        const float* __restrict__ a2_vb, const float* __restrict__ a2_kb,
        const float* __restrict__ a2_qb, const float* __restrict__ a2_ob,
        const float* __restrict__ qhb,
        float* __restrict__ out)
{
    extern __shared__ __align__(16) char sm[];
    const uint32_t base = s2u(sm);
    const uint32_t W0 = base + W0OFF, W1 = base + W1OFF;
    const uint32_t H = base + HOFF, T1 = base + T1OFF, T2 = base + T2OFF;
    const int tid = threadIdx.x, w = tid >> 5, lane = tid & 31;
    const int b0 = blockIdx.x * 2;

    wcopy(W0, 0, tid);
    wcopy(W1, 1, tid);
    // x (f32 [64][256]) -> f16 tiles T1 (cols 0-127), T2 (cols 128-255)
#pragma unroll
    for (int it = 0; it < 16; ++it) {
        int idx = tid + 256 * it;
        int r = idx >> 6, c4 = idx & 63;
        int col = 4 * c4;
        float4 v = *reinterpret_cast<const float4*>(
            x + (((size_t)b0 + (r >> 5)) * 32 + (r & 31)) * 256 + col);
        uint32_t dst = (col < 128 ? T1 : T2) + AS(r, col & 127);
        sts64(dst, pack2(v.x, v.y), pack2(v.z, v.w));
    }
    CP_WAIT();
    __syncthreads();

    // encoder (K=256): two accumulating passes
    {
        float aE[2][4][4];
        zacc<4>(aE);
        gemm_w8(aE, T1, W0, w, lane);
        gemm_w8(aE, T2, W1, w, lane);
        __syncthreads();                    // protect W0/W1 overwrite
        wcopy(W0, 2, tid);
        wcopy(W1, 3, tid);
        epi4(H, aE, enc_b, true, w, lane);
        CP_WAIT();
        __syncthreads();
    }

    att_block<false>(H, T1, T2, W0, W1, a1_kb, a1_qb, a1_vb, a1_ob,
                     mask, b0, 4, 5, 6, w, lane, tid);
    att_block<true>(H, T1, T2, W0, W1, a2_kb, a2_qb, a2_vb, a2_ob,
                    mask, b0, 8, 9, 10, w, lane, tid);

    // head: N=32, 8 warps x n8; B = W0 (tile 10 = qhw) via ldsm x2 trans
    {
        const int arow = (w & 1) * 32 + ((lane >> 3) & 1) * 8 + (lane & 7);
        const uint32_t abase = H + (uint32_t)arow * 256u;
        const uint32_t ax = (uint32_t)(arow & 7);
        const uint32_t atc = (uint32_t)((lane >> 4) & 1);
        const int kro2 = ((lane >> 3) & 1) * 8 + (lane & 7);
        const uint32_t bb = W0 + (uint32_t)kro2 * 256u;
        const uint32_t boH = (((uint32_t)(w >> 1) ^ (uint32_t)(lane & 7)) << 4);
        float acc[2][4];
#pragma unroll
        for (int i = 0; i < 2; ++i)
#pragma unroll
            for (int k = 0; k < 4; ++k) acc[i][k] = 0.f;
#pragma unroll
        for (int s = 0; s < 8; ++s) {
            uint32_t ao = (((2u * (uint32_t)s + atc) ^ ax) << 4);
            uint32_t a0[4], a1[4], b[2];
            ldsm4(a0, abase + ao);
            ldsm4(a1, abase + 4096u + ao);
            ldsm2t(b, bb + (uint32_t)s * 4096u + boH);
            mma16(acc[0], a0, b[0], b[1]);
            mma16(acc[1], a1, b[0], b[1]);
        }
        const int r0 = (w & 1) * 32 + (lane >> 2);
        const int col = (w >> 1) * 8 + 2 * (lane & 3);
        float bb0 = __ldg(qhb + col), bb1 = __ldg(qhb + col + 1);
#pragma unroll
        for (int mi = 0; mi < 2; ++mi)
#pragma unroll
            for (int hh = 0; hh < 2; ++hh) {
                int r = r0 + 16 * mi + 8 * hh;
                float2 v = make_float2(acc[mi][2 * hh] + bb0, acc[mi][2 * hh + 1] + bb1);
                *reinterpret_cast<float2*>(
                    out + (((size_t)b0 + (r >> 5)) * 32 + (r & 31)) * 32 + col) = v;
            }
    }
}

// ---- prep: bake f32 weights into pre-swizzled f16 tile images ----
__global__ void wprep(const float* __restrict__ enc_w,
                      const float* __restrict__ k1, const float* __restrict__ q1,
                      const float* __restrict__ v1, const float* __restrict__ o1,
                      const float* __restrict__ k2, const float* __restrict__ q2,
                      const float* __restrict__ v2, const float* __restrict__ o2,
                      const float* __restrict__ hw)
{
    const int m = blockIdx.x, tid = threadIdx.x, w = tid >> 5, lane = tid & 31;
    unsigned char* dst = g_wtiles[m];
    const float* srcs[11] = { enc_w, enc_w + 128 * 128, k1, q1, v1, o1, k2, q2, v2, o2, hw };
    const float* src = srcs[m];
    if (m < 10) {
#pragma unroll
        for (int i = 0; i < 16; ++i) {
            int k = 16 * w + i;
            float4 v = __ldg(reinterpret_cast<const float4*>(src + (size_t)k * 128) + lane);
            int n = 4 * lane;
            uint32_t off = (uint32_t)k * 256u + ((((uint32_t)(n >> 3)) ^ (uint32_t)(k & 7)) << 4)
                           + (uint32_t)((n >> 2) & 1) * 8u;
            uint2 val = make_uint2(pack2(v.x, v.y), pack2(v.z, v.w));
            *reinterpret_cast<uint2*>(dst + off) = val;
        }
    } else {
        for (int i = tid; i < 2048; i += 256)
            reinterpret_cast<uint4*>(dst)[i] = make_uint4(0, 0, 0, 0);
        __syncthreads();
#pragma unroll
        for (int it = 0; it < 4; ++it) {
            int k = 16 * w + 4 * it + (lane >> 3);
            int n = 4 * (lane & 7);
            float4 v = __ldg(reinterpret_cast<const float4*>(src + (size_t)k * 32) + (lane & 7));
            uint32_t off = (uint32_t)k * 256u + ((((uint32_t)(n >> 3)) ^ (uint32_t)(k & 7)) << 4)
                           + (uint32_t)((n >> 2) & 1) * 8u;
            uint2 val = make_uint2(pack2(v.x, v.y), pack2(v.z, v.w));
            *reinterpret_cast<uint2*>(dst + off) = val;
        }
    }
}

extern "C" void kernel_launch(void* const* d_in, const int* in_sizes, int n_in,
                              void* d_out, int out_size)
{
    const float* x     = (const float*)d_in[0];
    const float* mask  = (const float*)d_in[1];
    const float* enc_w = (const float*)d_in[2];
    const float* enc_b = (const float*)d_in[3];
    const float* a1_vw = (const float*)d_in[4];
    const float* a1_vb = (const float*)d_in[5];
    const float* a1_kw = (const float*)d_in[6];
    const float* a1_kb = (const float*)d_in[7];
    const float* a1_qw = (const float*)d_in[8];
    const float* a1_qb = (const float*)d_in[9];
    const float* a1_ow = (const float*)d_in[10];
    const float* a1_ob = (const float*)d_in[11];
    const float* a2_vw = (const float*)d_in[12];
    const float* a2_vb = (const float*)d_in[13];
    const float* a2_kw = (const float*)d_in[14];
    const float* a2_kb = (const float*)d_in[15];
    const float* a2_qw = (const float*)d_in[16];
    const float* a2_qb = (const float*)d_in[17];
    const float* a2_ow = (const float*)d_in[18];
    const float* a2_ob = (const float*)d_in[19];
    const float* q_w   = (const float*)d_in[20];
    const float* q_b   = (const float*)d_in[21];

    wprep<<<11, 256>>>(enc_w, a1_kw, a1_qw, a1_vw, a1_ow,
                       a2_kw, a2_qw, a2_vw, a2_ow, q_w);

    cudaFuncSetAttribute(dgn_f16, cudaFuncAttributeMaxDynamicSharedMemorySize, SM_TOTAL);
    dgn_f16<<<2048, 256, SM_TOTAL>>>(
        x, mask, enc_b,
        a1_vb, a1_kb, a1_qb, a1_ob,
        a2_vb, a2_kb, a2_qb, a2_ob,
        q_b, (float*)d_out);
}

// round 12
// speedup vs baseline: 1.5976x; 1.0099x over previous
#include <cuda_runtime.h>
#include <cuda_fp16.h>
#include <cstdint>

// smem (bytes): W0,W1 = 32KB f16 weight tiles [k=128][n=128]; H,T1,T2 = 16KB f16 act tiles [64][128]
#define W0OFF 0
#define W1OFF 32768
#define HOFF  65536
#define T1OFF 81920
#define T2OFF 98304
#define SM_TOTAL 114688   // 112KB -> 2 CTAs/SM

// pre-swizzled f16 weight tile images (exact smem layout), built once per launch
__device__ __align__(16) unsigned char g_wtiles[11][32768];

// f16 tile swizzle: [row][col] (128 cols), row stride 256B, 16B-chunk XOR
__device__ __forceinline__ uint32_t AS(int r, int c) {
    return (uint32_t)(r * 256 + (((c >> 3) ^ (r & 7)) << 4) + (c & 7) * 2);
}
__device__ __forceinline__ uint32_t s2u(const void* p) {
    uint32_t a;
    asm("{ .reg .u64 t; cvta.to.shared.u64 t, %1; cvt.u32.u64 %0, t; }" : "=r"(a) : "l"(p));
    return a;
}
__device__ __forceinline__ uint32_t pack2(float a, float b) {
    __half2 h = __floats2half2_rn(a, b);
    return *reinterpret_cast<uint32_t*>(&h);
}
__device__ __forceinline__ void sts64(uint32_t a, uint32_t x, uint32_t y) {
    asm volatile("st.shared.v2.b32 [%0], {%1,%2};" :: "r"(a), "r"(x), "r"(y));
}
__device__ __forceinline__ void ldsm4(uint32_t r[4], uint32_t a) {
    asm volatile("ldmatrix.sync.aligned.m8n8.x4.shared.b16 {%0,%1,%2,%3}, [%4];"
        : "=r"(r[0]), "=r"(r[1]), "=r"(r[2]), "=r"(r[3]) : "r"(a));
}
__device__ __forceinline__ void ldsm4t(uint32_t r[4], uint32_t a) {
    asm volatile("ldmatrix.sync.aligned.m8n8.x4.trans.shared.b16 {%0,%1,%2,%3}, [%4];"
        : "=r"(r[0]), "=r"(r[1]), "=r"(r[2]), "=r"(r[3]) : "r"(a));
}
__device__ __forceinline__ void ldsm2t(uint32_t r[2], uint32_t a) {
    asm volatile("ldmatrix.sync.aligned.m8n8.x2.trans.shared.b16 {%0,%1}, [%2];"
        : "=r"(r[0]), "=r"(r[1]) : "r"(a));
}
// stmatrix x4: thread t supplies address for matrix t>>3, row t&7;
// data reg j of thread t -> matrix j (row t>>2, colpair t&3) — matches our C fragments
__device__ __forceinline__ void stsm4(uint32_t a, uint32_t r0, uint32_t r1,
                                      uint32_t r2, uint32_t r3) {
    asm volatile("stmatrix.sync.aligned.m8n8.x4.shared.b16 [%0], {%1,%2,%3,%4};"
        :: "r"(a), "r"(r0), "r"(r1), "r"(r2), "r"(r3));
}
__device__ __forceinline__ void mma16(float c[4], const uint32_t a[4], uint32_t b0, uint32_t b1) {
    asm volatile("mma.sync.aligned.m16n8k16.row.col.f32.f16.f16.f32 "
        "{%0,%1,%2,%3}, {%4,%5,%6,%7}, {%8,%9}, {%0,%1,%2,%3};"
        : "+f"(c[0]), "+f"(c[1]), "+f"(c[2]), "+f"(c[3])
        : "r"(a[0]), "r"(a[1]), "r"(a[2]), "r"(a[3]), "r"(b0), "r"(b1));
}
template<int NF>
__device__ __forceinline__ void zacc(float a[2][NF][4]) {
#pragma unroll
    for (int i = 0; i < 2; ++i)
#pragma unroll
        for (int j = 0; j < NF; ++j)
#pragma unroll
            for (int k = 0; k < 4; ++k) a[i][j][k] = 0.f;
}

// ---- async weight tile copy: linear 32KB, 8 x 16B per thread ----
__device__ __forceinline__ void wcopy(uint32_t dstS, int m, int tid) {
#pragma unroll
    for (int i = 0; i < 8; ++i) {
        uint32_t off = (uint32_t)(tid + 256 * i) * 16u;
        asm volatile("{ .reg .u64 gp; cvta.to.global.u64 gp, %1;\n\t"
                     "cp.async.cg.shared.global [%0], [gp], 16; }"
                     :: "r"(dstS + off), "l"(g_wtiles[m] + off));
    }
}
#define CP_COMMIT()      asm volatile("cp.async.commit_group;" ::: "memory")
#define CP_WAIT_GROUP(n) asm volatile("cp.async.wait_group %0;" :: "n"(n) : "memory")

// ---- GEMM: C[64x128] (+)= A[64x128] * W, A act tile, W weight tile [k][n] via ldsm.trans ----
__device__ __forceinline__ void gemm_w8(float acc[2][4][4], uint32_t At, uint32_t Wt,
                                        int w, int lane) {
    const int arow = (w & 1) * 32 + ((lane >> 3) & 1) * 8 + (lane & 7);
    const uint32_t abase = At + (uint32_t)arow * 256u;
    const uint32_t ax = (uint32_t)(arow & 7);
    const uint32_t atc = (uint32_t)((lane >> 4) & 1);
    const int kro = ((lane >> 4) & 1) * 8 + (lane & 7);
    const uint32_t kx = (uint32_t)(lane & 7);
    const uint32_t nch = 4u * (uint32_t)(w >> 1) + (uint32_t)((lane >> 3) & 1);
    const uint32_t bbase = Wt + (uint32_t)kro * 256u;
    const uint32_t bo0 = ((nch ^ kx) << 4), bo1 = (((nch + 2u) ^ kx) << 4);
#pragma unroll
    for (int s = 0; s < 8; ++s) {
        uint32_t ao = (((2u * (uint32_t)s + atc) ^ ax) << 4);
        uint32_t a0[4], a1[4], p[4], q[4];
        ldsm4(a0, abase + ao);
        ldsm4(a1, abase + 4096u + ao);
        ldsm4t(p, bbase + (uint32_t)s * 4096u + bo0);
        ldsm4t(q, bbase + (uint32_t)s * 4096u + bo1);
        mma16(acc[0][0], a0, p[0], p[2]); mma16(acc[1][0], a1, p[0], p[2]);
        mma16(acc[0][1], a0, p[1], p[3]); mma16(acc[1][1], a1, p[1], p[3]);
        mma16(acc[0][2], a0, q[0], q[2]); mma16(acc[1][2], a1, q[0], q[2]);
        mma16(acc[0][3], a0, q[1], q[3]); mma16(acc[1][3], a1, q[1], q[3]);
    }
}

// ---- fused dual GEMM (K and Q projections share A) ----
__device__ __forceinline__ void gemm_kq(float aK[2][4][4], float aQ[2][4][4],
                                        uint32_t At, uint32_t B0, uint32_t B1,
                                        int w, int lane) {
    const int arow = (w & 1) * 32 + ((lane >> 3) & 1) * 8 + (lane & 7);
    const uint32_t abase = At + (uint32_t)arow * 256u;
    const uint32_t ax = (uint32_t)(arow & 7);
    const uint32_t atc = (uint32_t)((lane >> 4) & 1);
    const int kro = ((lane >> 4) & 1) * 8 + (lane & 7);
    const uint32_t kx = (uint32_t)(lane & 7);
    const uint32_t nch = 4u * (uint32_t)(w >> 1) + (uint32_t)((lane >> 3) & 1);
    const uint32_t bb0 = B0 + (uint32_t)kro * 256u;
    const uint32_t bb1 = B1 + (uint32_t)kro * 256u;
    const uint32_t bo0 = ((nch ^ kx) << 4), bo1 = (((nch + 2u) ^ kx) << 4);
#pragma unroll
    for (int s = 0; s < 8; ++s) {
        uint32_t ao = (((2u * (uint32_t)s + atc) ^ ax) << 4);
        uint32_t a0[4], a1[4], p[4], q[4], r[4], t[4];
        ldsm4(a0, abase + ao);
        ldsm4(a1, abase + 4096u + ao);
        ldsm4t(p, bb0 + (uint32_t)s * 4096u + bo0);
        ldsm4t(q, bb0 + (uint32_t)s * 4096u + bo1);
        ldsm4t(r, bb1 + (uint32_t)s * 4096u + bo0);
        ldsm4t(t, bb1 + (uint32_t)s * 4096u + bo1);
        mma16(aK[0][0], a0, p[0], p[2]); mma16(aK[1][0], a1, p[0], p[2]);
        mma16(aK[0][1], a0, p[1], p[3]); mma16(aK[1][1], a1, p[1], p[3]);
        mma16(aK[0][2], a0, q[0], q[2]); mma16(aK[1][2], a1, q[0], q[2]);
        mma16(aK[0][3], a0, q[1], q[3]); mma16(aK[1][3], a1, q[1], q[3]);
        mma16(aQ[0][0], a0, r[0], r[2]); mma16(aQ[1][0], a1, r[0], r[2]);
        mma16(aQ[0][1], a0, r[1], r[3]); mma16(aQ[1][1], a1, r[1], r[3]);
        mma16(aQ[0][2], a0, t[0], t[2]); mma16(aQ[1][2], a1, t[0], t[2]);
        mma16(aQ[0][3], a0, t[1], t[3]); mma16(aQ[1][3], a1, t[1], t[3]);
    }
}

// ---- epilogue: fp32 acc -> f16 act tile via stmatrix (4 x stsm4) ----
__device__ __forceinline__ void epi4(uint32_t dst, float acc[2][4][4], const float* bias,
                                     bool relu, int w, int lane) {
    const uint32_t rl = (uint32_t)(lane & 7);
    const uint32_t ch = 4u * (uint32_t)(w >> 1) + (uint32_t)(lane >> 3);
    const uint32_t base = dst + (uint32_t)((w & 1) * 32) * 256u + rl * 256u + ((ch ^ rl) << 4);
    const int colb = (w >> 1) * 32 + 2 * (lane & 3);
    float b[4][2];
#pragma unroll
    for (int nf = 0; nf < 4; ++nf) {
        b[nf][0] = bias ? __ldg(bias + colb + 8 * nf)     : 0.f;
        b[nf][1] = bias ? __ldg(bias + colb + 8 * nf + 1) : 0.f;
    }
#pragma unroll
    for (int mi = 0; mi < 2; ++mi)
#pragma unroll
        for (int hh = 0; hh < 2; ++hh) {
            uint32_t r[4];
#pragma unroll
            for (int nf = 0; nf < 4; ++nf) {
                float v0 = acc[mi][nf][2 * hh + 0] + b[nf][0];
                float v1 = acc[mi][nf][2 * hh + 1] + b[nf][1];
                if (relu) { v0 = fmaxf(v0, 0.f); v1 = fmaxf(v1, 0.f); }
                r[nf] = pack2(v0, v1);
            }
            stsm4(base + (uint32_t)(16 * mi + 8 * hh) * 256u, r[0], r[1], r[2], r[3]);
        }
}

// ---- scores (diag) + in-register softmax + P->T2 (warps 0..3 only) ----
__device__ __forceinline__ void scores_softmax(uint32_t Qt, uint32_t Kt,
                                               const float* mask, int b0, int w, int lane) {
    const int g = w >> 1;
    const int gid = lane >> 2, ctig = lane & 3;
    const int arow = 16 * w + ((lane >> 3) & 1) * 8 + (lane & 7);
    const uint32_t abase = Qt + (uint32_t)arow * 256u;
    const uint32_t x7 = (uint32_t)(lane & 7);
    const uint32_t atc = (uint32_t)((lane >> 4) & 1);
    const int brow = 32 * g + ((lane >> 3) & 1) * 8 + (lane & 7);
    const uint32_t bb0 = Kt + (uint32_t)brow * 256u;
    const uint32_t bb1 = bb0 + 4096u;
    float aS[4][4];
#pragma unroll
    for (int j = 0; j < 4; ++j)
#pragma unroll
        for (int k = 0; k < 4; ++k) aS[j][k] = 0.f;
#pragma unroll
    for (int s = 0; s < 8; ++s) {
        uint32_t ao = (((2u * (uint32_t)s + atc) ^ x7) << 4);
        uint32_t qa[4], k0[4], k1[4];
        ldsm4(qa, abase + ao);
        ldsm4(k0, bb0 + ao);
        ldsm4(k1, bb1 + ao);
        mma16(aS[0], qa, k0[0], k0[2]);
        mma16(aS[1], qa, k0[1], k0[3]);
        mma16(aS[2], qa, k1[0], k1[2]);
        mma16(aS[3], qa, k1[1], k1[3]);
    }
    const float* mA = mask + (((size_t)(b0 + g)) * 32 + (16 * (w & 1) + gid)) * 32;
    const float* mB = mA + 8 * 32;
    float lA[8], lB[8];
#pragma unroll
    for (int nf = 0; nf < 4; ++nf)
#pragma unroll
        for (int e = 0; e < 2; ++e) {
            int cl = 8 * nf + 2 * ctig + e;
            float ma = __ldg(mA + cl), mb = __ldg(mB + cl);
            lA[2 * nf + e] = aS[nf][e]     * ma - 9e15f * (1.0f - ma);
            lB[2 * nf + e] = aS[nf][2 + e] * mb - 9e15f * (1.0f - mb);
        }
    float mxA = lA[0], mxB = lB[0];
#pragma unroll
    for (int j = 1; j < 8; ++j) { mxA = fmaxf(mxA, lA[j]); mxB = fmaxf(mxB, lB[j]); }
    mxA = fmaxf(mxA, __shfl_xor_sync(0xffffffffu, mxA, 1));
    mxA = fmaxf(mxA, __shfl_xor_sync(0xffffffffu, mxA, 2));
    mxB = fmaxf(mxB, __shfl_xor_sync(0xffffffffu, mxB, 1));
    mxB = fmaxf(mxB, __shfl_xor_sync(0xffffffffu, mxB, 2));
    float sA = 0.f, sB = 0.f;
#pragma unroll
    for (int j = 0; j < 8; ++j) {
        lA[j] = __expf(lA[j] - mxA); sA += lA[j];
        lB[j] = __expf(lB[j] - mxB); sB += lB[j];
    }
    sA += __shfl_xor_sync(0xffffffffu, sA, 1);
    sA += __shfl_xor_sync(0xffffffffu, sA, 2);
    sB += __shfl_xor_sync(0xffffffffu, sB, 1);
    sB += __shfl_xor_sync(0xffffffffu, sB, 2);
    float iA = 1.0f / sA, iB = 1.0f / sB;
    // P writeback via 2 x stmatrix: row-octs {16w, 16w+8}, col-octs 32g+8j
    const uint32_t rl = (uint32_t)(lane & 7);
    const uint32_t chp = 4u * (uint32_t)g + (uint32_t)(lane >> 3);
    const uint32_t pbase = Qt + (uint32_t)(16 * w) * 256u + rl * 256u + ((chp ^ rl) << 4);
    uint32_t rA[4], rB[4];
#pragma unroll
    for (int nf = 0; nf < 4; ++nf) {
        rA[nf] = pack2(lA[2 * nf] * iA, lA[2 * nf + 1] * iA);
        rB[nf] = pack2(lB[2 * nf] * iB, lB[2 * nf + 1] * iB);
    }
    stsm4(pbase,          rA[0], rA[1], rA[2], rA[3]);
    stsm4(pbase + 2048u,  rB[0], rB[1], rB[2], rB[3]);
}

// ---- PV (diag, K=32): A = P (T2), B = V (H) via trans ----
__device__ __forceinline__ void gemm_pv(float acc[2][4][4], uint32_t Pt, uint32_t Vt,
                                        int w, int lane) {
    const int b = w & 1;
    const int arow = 32 * b + ((lane >> 3) & 1) * 8 + (lane & 7);
    const uint32_t abase = Pt + (uint32_t)arow * 256u;
    const uint32_t ax = (uint32_t)(arow & 7);
    const uint32_t atc = (uint32_t)((lane >> 4) & 1);
    const int kro = ((lane >> 4) & 1) * 8 + (lane & 7);
    const uint32_t kx = (uint32_t)(lane & 7);
    const uint32_t nch = 4u * (uint32_t)(w >> 1) + (uint32_t)((lane >> 3) & 1);
    const uint32_t bbase = Vt + (uint32_t)(32 * b + kro) * 256u;
    const uint32_t bo0 = ((nch ^ kx) << 4), bo1 = (((nch + 2u) ^ kx) << 4);
#pragma unroll
    for (int s = 0; s < 2; ++s) {
        uint32_t ach = 4u * (uint32_t)b + 2u * (uint32_t)s + atc;
        uint32_t ao = ((ach ^ ax) << 4);
        uint32_t a0[4], a1[4], p[4], q[4];
        ldsm4(a0, abase + ao);
        ldsm4(a1, abase + 4096u + ao);
        ldsm4t(p, bbase + (uint32_t)s * 4096u + bo0);
        ldsm4t(q, bbase + (uint32_t)s * 4096u + bo1);
        mma16(acc[0][0], a0, p[0], p[2]); mma16(acc[1][0], a1, p[0], p[2]);
        mma16(acc[0][1], a0, p[1], p[3]); mma16(acc[1][1], a1, p[1], p[3]);
        mma16(acc[0][2], a0, q[0], q[2]); mma16(acc[1][2], a1, q[0], q[2]);
        mma16(acc[0][3], a0, q[1], q[3]); mma16(acc[1][3], a1, q[1], q[3]);
    }
}

template<bool LAST>
__device__ __forceinline__ void att_block(
    uint32_t H, uint32_t T1, uint32_t T2, uint32_t W0, uint32_t W1,
    const float* kb, const float* qb, const float* vb, const float* ob,
    const float* mask, int b0, int mv, int mo, int mn1, int nq,
    int w, int lane, int tid)
{
    {   // P1: K, Q projections (fused)
        float aK[2][4][4], aQ[2][4][4];
        zacc<4>(aK); zacc<4>(aQ);
        gemm_kq(aK, aQ, H, W0, W1, w, lane);
        __syncthreads();                    // protect W0/W1 overwrite
        wcopy(W0, mv, tid); CP_COMMIT();    // pending: [vw]
        wcopy(W1, mo, tid); CP_COMMIT();    // pending: [vw][ow]
        epi4(T1, aK, kb, true, w, lane);    // K -> T1 [j][h]
        epi4(T2, aQ, qb, true, w, lane);    // Q -> T2 [i][h]
        CP_WAIT_GROUP(1);                   // vw done; ow still in flight (read in P4)
        __syncthreads();
    }
    {   // P2: V projection; scores+softmax on warps 0-3 (P overwrites own Q rows in T2)
        float aV[2][4][4];
        zacc<4>(aV);
        gemm_w8(aV, H, W0, w, lane);
        __syncthreads();                    // protect W0 overwrite + H write
        wcopy(W0, mn1, tid); CP_COMMIT();   // pending: [ow][kw'] (kw' read next block P1)
        epi4(H, aV, vb, true, w, lane);     // V -> H [j][h]
        if (w < 4) scores_softmax(T2, T1, mask, b0, w, lane);
        __syncthreads();                    // no cp wait needed here
    }
    {   // P3: PV (diag) -> T1 (no internal barrier; see R11 audit)
        float aP[2][4][4];
        zacc<4>(aP);
        gemm_pv(aP, T2, H, w, lane);
        epi4(T1, aP, nullptr, false, w, lane);
        CP_WAIT_GROUP(1);                   // ow done before P4 reads W1; kw' in flight
        __syncthreads();
    }
    {   // P4: out projection -> H
        float aO[2][4][4];
        zacc<4>(aO);
        gemm_w8(aO, T1, W1, w, lane);
        __syncthreads();                    // protect W1 overwrite + H write
        if (!LAST) { wcopy(W1, nq, tid); CP_COMMIT(); }  // pending: [kw'][qw']
        epi4(H, aO, ob, true, w, lane);
        CP_WAIT_GROUP(0);                   // everything ready for next block / head
        __syncthreads();
    }
}

__global__ void __launch_bounds__(256, 2)
dgn_f16(const float* __restrict__ x, const float* __restrict__ mask,
        const float* __restrict__ enc_b,
        const float* __restrict__ a1_vb, const float* __restrict__ a1_kb,
        const float* __restrict__ a1_qb, const float* __restrict__ a1_ob,
        const float* __restrict__ a2_vb, const float* __restrict__ a2_kb,
        const float* __restrict__ a2_qb, const float* __restrict__ a2_ob,
        const float* __restrict__ qhb,
        float* __restrict__ out)
{
    extern __shared__ __align__(16) char sm[];
    const uint32_t base = s2u(sm);
    const uint32_t W0 = base + W0OFF, W1 = base + W1OFF;
    const uint32_t H = base + HOFF, T1 = base + T1OFF, T2 = base + T2OFF;
    const int tid = threadIdx.x, w = tid >> 5, lane = tid & 31;
    const int b0 = blockIdx.x * 2;

    wcopy(W0, 0, tid); CP_COMMIT();
    wcopy(W1, 1, tid); CP_COMMIT();
    // x (f32 [64][256]) -> f16 tiles T1 (cols 0-127), T2 (cols 128-255)
#pragma unroll
    for (int it = 0; it < 16; ++it) {
        int idx = tid + 256 * it;
        int r = idx >> 6, c4 = idx & 63;
        int col = 4 * c4;
        float4 v = *reinterpret_cast<const float4*>(
            x + (((size_t)b0 + (r >> 5)) * 32 + (r & 31)) * 256 + col);
        uint32_t dst = (col < 128 ? T1 : T2) + AS(r, col & 127);
        sts64(dst, pack2(v.x, v.y), pack2(v.z, v.w));
    }
    CP_WAIT_GROUP(0);
    __syncthreads();

    // encoder (K=256): two accumulating passes
    {
        float aE[2][4][4];
        zacc<4>(aE);
        gemm_w8(aE, T1, W0, w, lane);
        gemm_w8(aE, T2, W1, w, lane);
        __syncthreads();                    // protect W0/W1 overwrite
        wcopy(W0, 2, tid); CP_COMMIT();
        wcopy(W1, 3, tid); CP_COMMIT();
        epi4(H, aE, enc_b, true, w, lane);
        CP_WAIT_GROUP(0);                   // both tiles read immediately in P1
        __syncthreads();
    }

    att_block<false>(H, T1, T2, W0, W1, a1_kb, a1_qb, a1_vb, a1_ob,
                     mask, b0, 4, 5, 6, 7, w, lane, tid);
    att_block<true>(H, T1, T2, W0, W1, a2_kb, a2_qb, a2_vb, a2_ob,
                    mask, b0, 8, 9, 10, -1, w, lane, tid);

    // head: N=32, 8 warps x n8; B = W0 (tile 10 = qhw) via ldsm x2 trans
    {
        const int arow = (w & 1) * 32 + ((lane >> 3) & 1) * 8 + (lane & 7);
        const uint32_t abase = H + (uint32_t)arow * 256u;
        const uint32_t ax = (uint32_t)(arow & 7);
        const uint32_t atc = (uint32_t)((lane >> 4) & 1);
        const int kro2 = ((lane >> 3) & 1) * 8 + (lane & 7);
        const uint32_t bb = W0 + (uint32_t)kro2 * 256u;
        const uint32_t boH = (((uint32_t)(w >> 1) ^ (uint32_t)(lane & 7)) << 4);
        float acc[2][4];
#pragma unroll
        for (int i = 0; i < 2; ++i)
#pragma unroll
            for (int k = 0; k < 4; ++k) acc[i][k] = 0.f;
#pragma unroll
        for (int s = 0; s < 8; ++s) {
            uint32_t ao = (((2u * (uint32_t)s + atc) ^ ax) << 4);
            uint32_t a0[4], a1[4], b[2];
            ldsm4(a0, abase + ao);
            ldsm4(a1, abase + 4096u + ao);
            ldsm2t(b, bb + (uint32_t)s * 4096u + boH);
            mma16(acc[0], a0, b[0], b[1]);
            mma16(acc[1], a1, b[0], b[1]);
        }
        const int r0 = (w & 1) * 32 + (lane >> 2);
        const int col = (w >> 1) * 8 + 2 * (lane & 3);
        float bb0 = __ldg(qhb + col), bb1 = __ldg(qhb + col + 1);
#pragma unroll
        for (int mi = 0; mi < 2; ++mi)
#pragma unroll
            for (int hh = 0; hh < 2; ++hh) {
                int r = r0 + 16 * mi + 8 * hh;
                float2 v = make_float2(acc[mi][2 * hh] + bb0, acc[mi][2 * hh + 1] + bb1);
                *reinterpret_cast<float2*>(
                    out + (((size_t)b0 + (r >> 5)) * 32 + (r & 31)) * 32 + col) = v;
            }
    }
}

// ---- prep: bake f32 weights into pre-swizzled f16 tile images ----
__global__ void wprep(const float* __restrict__ enc_w,
                      const float* __restrict__ k1, const float* __restrict__ q1,
                      const float* __restrict__ v1, const float* __restrict__ o1,
                      const float* __restrict__ k2, const float* __restrict__ q2,
                      const float* __restrict__ v2, const float* __restrict__ o2,
                      const float* __restrict__ hw)
{
    const int m = blockIdx.x, tid = threadIdx.x, w = tid >> 5, lane = tid & 31;
    unsigned char* dst = g_wtiles[m];
    const float* srcs[11] = { enc_w, enc_w + 128 * 128, k1, q1, v1, o1, k2, q2, v2, o2, hw };
    const float* src = srcs[m];
    if (m < 10) {
#pragma unroll
        for (int i = 0; i < 16; ++i) {
            int k = 16 * w + i;
            float4 v = __ldg(reinterpret_cast<const float4*>(src + (size_t)k * 128) + lane);
            int n = 4 * lane;
            uint32_t off = (uint32_t)k * 256u + ((((uint32_t)(n >> 3)) ^ (uint32_t)(k & 7)) << 4)
                           + (uint32_t)((n >> 2) & 1) * 8u;
            uint2 val = make_uint2(pack2(v.x, v.y), pack2(v.z, v.w));
            *reinterpret_cast<uint2*>(dst + off) = val;
        }
    } else {
        for (int i = tid; i < 2048; i += 256)
            reinterpret_cast<uint4*>(dst)[i] = make_uint4(0, 0, 0, 0);
        __syncthreads();
#pragma unroll
        for (int it = 0; it < 4; ++it) {
            int k = 16 * w + 4 * it + (lane >> 3);
            int n = 4 * (lane & 7);
            float4 v = __ldg(reinterpret_cast<const float4*>(src + (size_t)k * 32) + (lane & 7));
            uint32_t off = (uint32_t)k * 256u + ((((uint32_t)(n >> 3)) ^ (uint32_t)(k & 7)) << 4)
                           + (uint32_t)((n >> 2) & 1) * 8u;
            uint2 val = make_uint2(pack2(v.x, v.y), pack2(v.z, v.w));
            *reinterpret_cast<uint2*>(dst + off) = val;
        }
    }
}

extern "C" void kernel_launch(void* const* d_in, const int* in_sizes, int n_in,
                              void* d_out, int out_size)
{
    const float* x     = (const float*)d_in[0];
    const float* mask  = (const float*)d_in[1];
    const float* enc_w = (const float*)d_in[2];
    const float* enc_b = (const float*)d_in[3];
    const float* a1_vw = (const float*)d_in[4];
    const float* a1_vb = (const float*)d_in[5];
    const float* a1_kw = (const float*)d_in[6];
    const float* a1_kb = (const float*)d_in[7];
    const float* a1_qw = (const float*)d_in[8];
    const float* a1_qb = (const float*)d_in[9];
    const float* a1_ow = (const float*)d_in[10];
    const float* a1_ob = (const float*)d_in[11];
    const float* a2_vw = (const float*)d_in[12];
    const float* a2_vb = (const float*)d_in[13];
    const float* a2_kw = (const float*)d_in[14];
    const float* a2_kb = (const float*)d_in[15];
    const float* a2_qw = (const float*)d_in[16];
    const float* a2_qb = (const float*)d_in[17];
    const float* a2_ow = (const float*)d_in[18];
    const float* a2_ob = (const float*)d_in[19];
    const float* q_w   = (const float*)d_in[20];
    const float* q_b   = (const float*)d_in[21];

    wprep<<<11, 256>>>(enc_w, a1_kw, a1_qw, a1_vw, a1_ow,
                       a2_kw, a2_qw, a2_vw, a2_ow, q_w);

    cudaFuncSetAttribute(dgn_f16, cudaFuncAttributeMaxDynamicSharedMemorySize, SM_TOTAL);
    dgn_f16<<<2048, 256, SM_TOTAL>>>(
        x, mask, enc_b,
        a1_vb, a1_kb, a1_qb, a1_ob,
        a2_vb, a2_kb, a2_qb, a2_ob,
        q_b, (float*)d_out);
}

// round 13
// speedup vs baseline: 1.6214x; 1.0149x over previous
#include <cuda_runtime.h>
#include <cuda_fp16.h>
#include <cstdint>

// smem (bytes): W0,W1 = 32KB f16 weight tiles [k=128][n=128]; H,T1,T2 = 16KB f16 act tiles [64][128]
#define W0OFF 0
#define W1OFF 32768
#define HOFF  65536
#define T1OFF 81920
#define T2OFF 98304
#define SM_TOTAL 114688   // 112KB -> 2 CTAs/SM

// pre-swizzled f16 weight tile images (exact smem layout), built once per launch
__device__ __align__(16) unsigned char g_wtiles[11][32768];
// bit-packed mask: one uint32 per (batch,row)
__device__ uint32_t g_maskbits[4096 * 32];

// f16 tile swizzle: [row][col] (128 cols), row stride 256B, 16B-chunk XOR
__device__ __forceinline__ uint32_t AS(int r, int c) {
    return (uint32_t)(r * 256 + (((c >> 3) ^ (r & 7)) << 4) + (c & 7) * 2);
}
__device__ __forceinline__ uint32_t s2u(const void* p) {
    uint32_t a;
    asm("{ .reg .u64 t; cvta.to.shared.u64 t, %1; cvt.u32.u64 %0, t; }" : "=r"(a) : "l"(p));
    return a;
}
__device__ __forceinline__ uint32_t pack2(float a, float b) {
    __half2 h = __floats2half2_rn(a, b);
    return *reinterpret_cast<uint32_t*>(&h);
}
__device__ __forceinline__ void sts64(uint32_t a, uint32_t x, uint32_t y) {
    asm volatile("st.shared.v2.b32 [%0], {%1,%2};" :: "r"(a), "r"(x), "r"(y));
}
__device__ __forceinline__ void ldsm4(uint32_t r[4], uint32_t a) {
    asm volatile("ldmatrix.sync.aligned.m8n8.x4.shared.b16 {%0,%1,%2,%3}, [%4];"
        : "=r"(r[0]), "=r"(r[1]), "=r"(r[2]), "=r"(r[3]) : "r"(a));
}
__device__ __forceinline__ void ldsm4t(uint32_t r[4], uint32_t a) {
    asm volatile("ldmatrix.sync.aligned.m8n8.x4.trans.shared.b16 {%0,%1,%2,%3}, [%4];"
        : "=r"(r[0]), "=r"(r[1]), "=r"(r[2]), "=r"(r[3]) : "r"(a));
}
__device__ __forceinline__ void ldsm2t(uint32_t r[2], uint32_t a) {
    asm volatile("ldmatrix.sync.aligned.m8n8.x2.trans.shared.b16 {%0,%1}, [%2];"
        : "=r"(r[0]), "=r"(r[1]) : "r"(a));
}
__device__ __forceinline__ void stsm4(uint32_t a, uint32_t r0, uint32_t r1,
                                      uint32_t r2, uint32_t r3) {
    asm volatile("stmatrix.sync.aligned.m8n8.x4.shared.b16 [%0], {%1,%2,%3,%4};"
        :: "r"(a), "r"(r0), "r"(r1), "r"(r2), "r"(r3));
}
__device__ __forceinline__ void mma16(float c[4], const uint32_t a[4], uint32_t b0, uint32_t b1) {
    asm volatile("mma.sync.aligned.m16n8k16.row.col.f32.f16.f16.f32 "
        "{%0,%1,%2,%3}, {%4,%5,%6,%7}, {%8,%9}, {%0,%1,%2,%3};"
        : "+f"(c[0]), "+f"(c[1]), "+f"(c[2]), "+f"(c[3])
        : "r"(a[0]), "r"(a[1]), "r"(a[2]), "r"(a[3]), "r"(b0), "r"(b1));
}
template<int NF>
__device__ __forceinline__ void zacc(float a[2][NF][4]) {
#pragma unroll
    for (int i = 0; i < 2; ++i)
#pragma unroll
        for (int j = 0; j < NF; ++j)
#pragma unroll
            for (int k = 0; k < 4; ++k) a[i][j][k] = 0.f;
}

// ---- async weight tile copy: linear 32KB, 8 x 16B per thread ----
__device__ __forceinline__ void wcopy(uint32_t dstS, int m, int tid) {
#pragma unroll
    for (int i = 0; i < 8; ++i) {
        uint32_t off = (uint32_t)(tid + 256 * i) * 16u;
        asm volatile("{ .reg .u64 gp; cvta.to.global.u64 gp, %1;\n\t"
                     "cp.async.cg.shared.global [%0], [gp], 16; }"
                     :: "r"(dstS + off), "l"(g_wtiles[m] + off));
    }
}
#define CP_COMMIT()      asm volatile("cp.async.commit_group;" ::: "memory")
#define CP_WAIT_GROUP(n) asm volatile("cp.async.wait_group %0;" :: "n"(n) : "memory")

// ---- GEMM: C[64x128] (+)= A[64x128] * W, A act tile, W weight tile [k][n] via ldsm.trans ----
__device__ __forceinline__ void gemm_w8(float acc[2][4][4], uint32_t At, uint32_t Wt,
                                        int w, int lane) {
    const int arow = (w & 1) * 32 + ((lane >> 3) & 1) * 8 + (lane & 7);
    const uint32_t abase = At + (uint32_t)arow * 256u;
    const uint32_t ax = (uint32_t)(arow & 7);
    const uint32_t atc = (uint32_t)((lane >> 4) & 1);
    const int kro = ((lane >> 4) & 1) * 8 + (lane & 7);
    const uint32_t kx = (uint32_t)(lane & 7);
    const uint32_t nch = 4u * (uint32_t)(w >> 1) + (uint32_t)((lane >> 3) & 1);
    const uint32_t bbase = Wt + (uint32_t)kro * 256u;
    const uint32_t bo0 = ((nch ^ kx) << 4), bo1 = (((nch + 2u) ^ kx) << 4);
#pragma unroll
    for (int s = 0; s < 8; ++s) {
        uint32_t ao = (((2u * (uint32_t)s + atc) ^ ax) << 4);
        uint32_t a0[4], a1[4], p[4], q[4];
        ldsm4(a0, abase + ao);
        ldsm4(a1, abase + 4096u + ao);
        ldsm4t(p, bbase + (uint32_t)s * 4096u + bo0);
        ldsm4t(q, bbase + (uint32_t)s * 4096u + bo1);
        mma16(acc[0][0], a0, p[0], p[2]); mma16(acc[1][0], a1, p[0], p[2]);
        mma16(acc[0][1], a0, p[1], p[3]); mma16(acc[1][1], a1, p[1], p[3]);
        mma16(acc[0][2], a0, q[0], q[2]); mma16(acc[1][2], a1, q[0], q[2]);
        mma16(acc[0][3], a0, q[1], q[3]); mma16(acc[1][3], a1, q[1], q[3]);
    }
}

// ---- fused dual GEMM (K and Q projections share A) ----
__device__ __forceinline__ void gemm_kq(float aK[2][4][4], float aQ[2][4][4],
                                        uint32_t At, uint32_t B0, uint32_t B1,
                                        int w, int lane) {
    const int arow = (w & 1) * 32 + ((lane >> 3) & 1) * 8 + (lane & 7);
    const uint32_t abase = At + (uint32_t)arow * 256u;
    const uint32_t ax = (uint32_t)(arow & 7);
    const uint32_t atc = (uint32_t)((lane >> 4) & 1);
    const int kro = ((lane >> 4) & 1) * 8 + (lane & 7);
    const uint32_t kx = (uint32_t)(lane & 7);
    const uint32_t nch = 4u * (uint32_t)(w >> 1) + (uint32_t)((lane >> 3) & 1);
    const uint32_t bb0 = B0 + (uint32_t)kro * 256u;
    const uint32_t bb1 = B1 + (uint32_t)kro * 256u;
    const uint32_t bo0 = ((nch ^ kx) << 4), bo1 = (((nch + 2u) ^ kx) << 4);
#pragma unroll
    for (int s = 0; s < 8; ++s) {
        uint32_t ao = (((2u * (uint32_t)s + atc) ^ ax) << 4);
        uint32_t a0[4], a1[4], p[4], q[4], r[4], t[4];
        ldsm4(a0, abase + ao);
        ldsm4(a1, abase + 4096u + ao);
        ldsm4t(p, bb0 + (uint32_t)s * 4096u + bo0);
        ldsm4t(q, bb0 + (uint32_t)s * 4096u + bo1);
        ldsm4t(r, bb1 + (uint32_t)s * 4096u + bo0);
        ldsm4t(t, bb1 + (uint32_t)s * 4096u + bo1);
        mma16(aK[0][0], a0, p[0], p[2]); mma16(aK[1][0], a1, p[0], p[2]);
        mma16(aK[0][1], a0, p[1], p[3]); mma16(aK[1][1], a1, p[1], p[3]);
        mma16(aK[0][2], a0, q[0], q[2]); mma16(aK[1][2], a1, q[0], q[2]);
        mma16(aK[0][3], a0, q[1], q[3]); mma16(aK[1][3], a1, q[1], q[3]);
        mma16(aQ[0][0], a0, r[0], r[2]); mma16(aQ[1][0], a1, r[0], r[2]);
        mma16(aQ[0][1], a0, r[1], r[3]); mma16(aQ[1][1], a1, r[1], r[3]);
        mma16(aQ[0][2], a0, t[0], t[2]); mma16(aQ[1][2], a1, t[0], t[2]);
        mma16(aQ[0][3], a0, t[1], t[3]); mma16(aQ[1][3], a1, t[1], t[3]);
    }
}

// ---- fused V-projection + diag scores: all warps do V; warps 0-3 also accumulate
//      scores (Q rows 16w x K rows 32g) using the SAME ao offset ----
__device__ __forceinline__ void gemm_vs(float aV[2][4][4], float aS[4][4],
                                        uint32_t At, uint32_t Wt, uint32_t Qt, uint32_t Kt,
                                        int w, int lane) {
    const int arow = (w & 1) * 32 + ((lane >> 3) & 1) * 8 + (lane & 7);
    const uint32_t abase = At + (uint32_t)arow * 256u;
    const uint32_t ax = (uint32_t)(arow & 7);
    const uint32_t atc = (uint32_t)((lane >> 4) & 1);
    const int kro = ((lane >> 4) & 1) * 8 + (lane & 7);
    const uint32_t kx = (uint32_t)(lane & 7);
    const uint32_t nch = 4u * (uint32_t)(w >> 1) + (uint32_t)((lane >> 3) & 1);
    const uint32_t bbase = Wt + (uint32_t)kro * 256u;
    const uint32_t bo0 = ((nch ^ kx) << 4), bo1 = (((nch + 2u) ^ kx) << 4);
    // scores geometry (valid for w<4): Q rows 16w.., K rows 32*(w>>1)..
    const uint32_t qbase = Qt + (uint32_t)(16 * w + ((lane >> 3) & 1) * 8 + (lane & 7)) * 256u;
    const uint32_t kb0 = Kt + (uint32_t)(32 * (w >> 1) + ((lane >> 3) & 1) * 8 + (lane & 7)) * 256u;
    const uint32_t kb1 = kb0 + 4096u;
#pragma unroll
    for (int s = 0; s < 8; ++s) {
        uint32_t ao = (((2u * (uint32_t)s + atc) ^ ax) << 4);
        uint32_t a0[4], a1[4], p[4], q[4];
        ldsm4(a0, abase + ao);
        ldsm4(a1, abase + 4096u + ao);
        ldsm4t(p, bbase + (uint32_t)s * 4096u + bo0);
        ldsm4t(q, bbase + (uint32_t)s * 4096u + bo1);
        if (w < 4) {
            uint32_t qa[4], k0[4], k1[4];
            ldsm4(qa, qbase + ao);
            ldsm4(k0, kb0 + ao);
            ldsm4(k1, kb1 + ao);
            mma16(aS[0], qa, k0[0], k0[2]);
            mma16(aS[1], qa, k0[1], k0[3]);
            mma16(aS[2], qa, k1[0], k1[2]);
            mma16(aS[3], qa, k1[1], k1[3]);
        }
        mma16(aV[0][0], a0, p[0], p[2]); mma16(aV[1][0], a1, p[0], p[2]);
        mma16(aV[0][1], a0, p[1], p[3]); mma16(aV[1][1], a1, p[1], p[3]);
        mma16(aV[0][2], a0, q[0], q[2]); mma16(aV[1][2], a1, q[0], q[2]);
        mma16(aV[0][3], a0, q[1], q[3]); mma16(aV[1][3], a1, q[1], q[3]);
    }
}

// ---- epilogue: fp32 acc -> f16 act tile via stmatrix (4 x stsm4) ----
__device__ __forceinline__ void epi4(uint32_t dst, float acc[2][4][4], const float* bias,
                                     bool relu, int w, int lane) {
    const uint32_t rl = (uint32_t)(lane & 7);
    const uint32_t ch = 4u * (uint32_t)(w >> 1) + (uint32_t)(lane >> 3);
    const uint32_t base = dst + (uint32_t)((w & 1) * 32) * 256u + rl * 256u + ((ch ^ rl) << 4);
    const int colb = (w >> 1) * 32 + 2 * (lane & 3);
    float b[4][2];
#pragma unroll
    for (int nf = 0; nf < 4; ++nf) {
        b[nf][0] = bias ? __ldg(bias + colb + 8 * nf)     : 0.f;
        b[nf][1] = bias ? __ldg(bias + colb + 8 * nf + 1) : 0.f;
    }
#pragma unroll
    for (int mi = 0; mi < 2; ++mi)
#pragma unroll
        for (int hh = 0; hh < 2; ++hh) {
            uint32_t r[4];
#pragma unroll
            for (int nf = 0; nf < 4; ++nf) {
                float v0 = acc[mi][nf][2 * hh + 0] + b[nf][0];
                float v1 = acc[mi][nf][2 * hh + 1] + b[nf][1];
                if (relu) { v0 = fmaxf(v0, 0.f); v1 = fmaxf(v1, 0.f); }
                r[nf] = pack2(v0, v1);
            }
            stsm4(base + (uint32_t)(16 * mi + 8 * hh) * 256u, r[0], r[1], r[2], r[3]);
        }
}

// ---- register softmax on diag scores + P writeback (warps 0..3) ----
__device__ __forceinline__ void softmax_reg(uint32_t Qt, float aS[4][4],
                                            int b0, int w, int lane) {
    const int g = w >> 1;
    const int gid = lane >> 2, ctig = lane & 3;
    const int rowA = 16 * (w & 1) + gid;             // batch-local row
    const uint32_t bA = __ldg(&g_maskbits[((size_t)(b0 + g)) * 32 + rowA]);
    const uint32_t bB = __ldg(&g_maskbits[((size_t)(b0 + g)) * 32 + rowA + 8]);
    float lA[8], lB[8];
#pragma unroll
    for (int nf = 0; nf < 4; ++nf)
#pragma unroll
        for (int e = 0; e < 2; ++e) {
            int cl = 8 * nf + 2 * ctig + e;
            lA[2 * nf + e] = ((bA >> cl) & 1u) ? aS[nf][e]     : -9e15f;
            lB[2 * nf + e] = ((bB >> cl) & 1u) ? aS[nf][2 + e] : -9e15f;
        }
    float mxA = lA[0], mxB = lB[0];
#pragma unroll
    for (int j = 1; j < 8; ++j) { mxA = fmaxf(mxA, lA[j]); mxB = fmaxf(mxB, lB[j]); }
    mxA = fmaxf(mxA, __shfl_xor_sync(0xffffffffu, mxA, 1));
    mxA = fmaxf(mxA, __shfl_xor_sync(0xffffffffu, mxA, 2));
    mxB = fmaxf(mxB, __shfl_xor_sync(0xffffffffu, mxB, 1));
    mxB = fmaxf(mxB, __shfl_xor_sync(0xffffffffu, mxB, 2));
    float sA = 0.f, sB = 0.f;
#pragma unroll
    for (int j = 0; j < 8; ++j) {
        lA[j] = __expf(lA[j] - mxA); sA += lA[j];
        lB[j] = __expf(lB[j] - mxB); sB += lB[j];
    }
    sA += __shfl_xor_sync(0xffffffffu, sA, 1);
    sA += __shfl_xor_sync(0xffffffffu, sA, 2);
    sB += __shfl_xor_sync(0xffffffffu, sB, 1);
    sB += __shfl_xor_sync(0xffffffffu, sB, 2);
    float iA = 1.0f / sA, iB = 1.0f / sB;
    // P writeback via 2 x stmatrix: row-octs {16w, 16w+8}, col-octs 32g+8j
    const uint32_t rl = (uint32_t)(lane & 7);
    const uint32_t chp = 4u * (uint32_t)g + (uint32_t)(lane >> 3);
    const uint32_t pbase = Qt + (uint32_t)(16 * w) * 256u + rl * 256u + ((chp ^ rl) << 4);
    uint32_t rA[4], rB[4];
#pragma unroll
    for (int nf = 0; nf < 4; ++nf) {
        rA[nf] = pack2(lA[2 * nf] * iA, lA[2 * nf + 1] * iA);
        rB[nf] = pack2(lB[2 * nf] * iB, lB[2 * nf + 1] * iB);
    }
    stsm4(pbase,         rA[0], rA[1], rA[2], rA[3]);
    stsm4(pbase + 2048u, rB[0], rB[1], rB[2], rB[3]);
}

// ---- PV (diag, K=32): A = P (T2), B = V (H) via trans ----
__device__ __forceinline__ void gemm_pv(float acc[2][4][4], uint32_t Pt, uint32_t Vt,
                                        int w, int lane) {
    const int b = w & 1;
    const int arow = 32 * b + ((lane >> 3) & 1) * 8 + (lane & 7);
    const uint32_t abase = Pt + (uint32_t)arow * 256u;
    const uint32_t ax = (uint32_t)(arow & 7);
    const uint32_t atc = (uint32_t)((lane >> 4) & 1);
    const int kro = ((lane >> 4) & 1) * 8 + (lane & 7);
    const uint32_t kx = (uint32_t)(lane & 7);
    const uint32_t nch = 4u * (uint32_t)(w >> 1) + (uint32_t)((lane >> 3) & 1);
    const uint32_t bbase = Vt + (uint32_t)(32 * b + kro) * 256u;
    const uint32_t bo0 = ((nch ^ kx) << 4), bo1 = (((nch + 2u) ^ kx) << 4);
#pragma unroll
    for (int s = 0; s < 2; ++s) {
        uint32_t ach = 4u * (uint32_t)b + 2u * (uint32_t)s + atc;
        uint32_t ao = ((ach ^ ax) << 4);
        uint32_t a0[4], a1[4], p[4], q[4];
        ldsm4(a0, abase + ao);
        ldsm4(a1, abase + 4096u + ao);
        ldsm4t(p, bbase + (uint32_t)s * 4096u + bo0);
        ldsm4t(q, bbase + (uint32_t)s * 4096u + bo1);
        mma16(acc[0][0], a0, p[0], p[2]); mma16(acc[1][0], a1, p[0], p[2]);
        mma16(acc[0][1], a0, p[1], p[3]); mma16(acc[1][1], a1, p[1], p[3]);
        mma16(acc[0][2], a0, q[0], q[2]); mma16(acc[1][2], a1, q[0], q[2]);
        mma16(acc[0][3], a0, q[1], q[3]); mma16(acc[1][3], a1, q[1], q[3]);
    }
}

template<bool LAST>
__device__ __forceinline__ void att_block(
    uint32_t H, uint32_t T1, uint32_t T2, uint32_t W0, uint32_t W1,
    const float* kb, const float* qb, const float* vb, const float* ob,
    int b0, int mv, int mo, int mn1, int nq,
    int w, int lane, int tid)
{
    {   // P1: K, Q projections (fused)
        float aK[2][4][4], aQ[2][4][4];
        zacc<4>(aK); zacc<4>(aQ);
        gemm_kq(aK, aQ, H, W0, W1, w, lane);
        __syncthreads();                    // protect W0/W1 overwrite
        wcopy(W0, mv, tid); CP_COMMIT();    // pending: [vw]
        wcopy(W1, mo, tid); CP_COMMIT();    // pending: [vw][ow]
        epi4(T1, aK, kb, true, w, lane);    // K -> T1 [j][h]
        epi4(T2, aQ, qb, true, w, lane);    // Q -> T2 [i][h]
        CP_WAIT_GROUP(1);                   // vw done; ow still in flight (read in P4)
        __syncthreads();
    }
    {   // P2: V projection fused with diag scores (warps 0-3); softmax tail in regs
        float aV[2][4][4];
        float aS[4][4];
        zacc<4>(aV);
#pragma unroll
        for (int j = 0; j < 4; ++j)
#pragma unroll
            for (int k = 0; k < 4; ++k) aS[j][k] = 0.f;
        gemm_vs(aV, aS, H, W0, T2, T1, w, lane);
        __syncthreads();                    // protect W0 overwrite + H write
        wcopy(W0, mn1, tid); CP_COMMIT();   // pending: [ow][kw']
        epi4(H, aV, vb, true, w, lane);     // V -> H [j][h]
        if (w < 4) softmax_reg(T2, aS, b0, w, lane);   // P -> T2 (own Q rows)
        __syncthreads();
    }
    {   // P3: PV (diag) -> T1 (no internal barrier)
        float aP[2][4][4];
        zacc<4>(aP);
        gemm_pv(aP, T2, H, w, lane);
        epi4(T1, aP, nullptr, false, w, lane);
        CP_WAIT_GROUP(1);                   // ow done before P4 reads W1
        __syncthreads();
    }
    {   // P4: out projection -> H
        float aO[2][4][4];
        zacc<4>(aO);
        gemm_w8(aO, T1, W1, w, lane);
        __syncthreads();                    // protect W1 overwrite + H write
        if (!LAST) { wcopy(W1, nq, tid); CP_COMMIT(); }
        epi4(H, aO, ob, true, w, lane);
        CP_WAIT_GROUP(0);
        __syncthreads();
    }
}

__global__ void __launch_bounds__(256, 2)
dgn_f16(const float* __restrict__ x,
        const float* __restrict__ enc_b,
        const float* __restrict__ a1_vb, const float* __restrict__ a1_kb,
        const float* __restrict__ a1_qb, const float* __restrict__ a1_ob,
        const float* __restrict__ a2_vb, const float* __restrict__ a2_kb,
        const float* __restrict__ a2_qb, const float* __restrict__ a2_ob,
        const float* __restrict__ qhb,
        float* __restrict__ out)
{
    extern __shared__ __align__(16) char sm[];
    const uint32_t base = s2u(sm);
    const uint32_t W0 = base + W0OFF, W1 = base + W1OFF;
    const uint32_t H = base + HOFF, T1 = base + T1OFF, T2 = base + T2OFF;
    const int tid = threadIdx.x, w = tid >> 5, lane = tid & 31;
    const int b0 = blockIdx.x * 2;

    wcopy(W0, 0, tid); CP_COMMIT();
    wcopy(W1, 1, tid); CP_COMMIT();
    // x (f32 [64][256]) -> f16 tiles T1 (cols 0-127), T2 (cols 128-255)
#pragma unroll
    for (int it = 0; it < 16; ++it) {
        int idx = tid + 256 * it;
        int r = idx >> 6, c4 = idx & 63;
        int col = 4 * c4;
        float4 v = *reinterpret_cast<const float4*>(
            x + (((size_t)b0 + (r >> 5)) * 32 + (r & 31)) * 256 + col);
        uint32_t dst = (col < 128 ? T1 : T2) + AS(r, col & 127);
        sts64(dst, pack2(v.x, v.y), pack2(v.z, v.w));
    }
    CP_WAIT_GROUP(0);
    __syncthreads();

    // encoder (K=256): two accumulating passes
    {
        float aE[2][4][4];
        zacc<4>(aE);
        gemm_w8(aE, T1, W0, w, lane);
        gemm_w8(aE, T2, W1, w, lane);
        __syncthreads();                    // protect W0/W1 overwrite
        wcopy(W0, 2, tid); CP_COMMIT();
        wcopy(W1, 3, tid); CP_COMMIT();
        epi4(H, aE, enc_b, true, w, lane);
        CP_WAIT_GROUP(0);
        __syncthreads();
    }

    att_block<false>(H, T1, T2, W0, W1, a1_kb, a1_qb, a1_vb, a1_ob,
                     b0, 4, 5, 6, 7, w, lane, tid);
    att_block<true>(H, T1, T2, W0, W1, a2_kb, a2_qb, a2_vb, a2_ob,
                    b0, 8, 9, 10, -1, w, lane, tid);

    // head: N=32, 8 warps x n8; B = W0 (tile 10 = qhw) via ldsm x2 trans
    {
        const int arow = (w & 1) * 32 + ((lane >> 3) & 1) * 8 + (lane & 7);
        const uint32_t abase = H + (uint32_t)arow * 256u;
        const uint32_t ax = (uint32_t)(arow & 7);
        const uint32_t atc = (uint32_t)((lane >> 4) & 1);
        const int kro2 = ((lane >> 3) & 1) * 8 + (lane & 7);
        const uint32_t bb = W0 + (uint32_t)kro2 * 256u;
        const uint32_t boH = (((uint32_t)(w >> 1) ^ (uint32_t)(lane & 7)) << 4);
        float acc[2][4];
#pragma unroll
        for (int i = 0; i < 2; ++i)
#pragma unroll
            for (int k = 0; k < 4; ++k) acc[i][k] = 0.f;
#pragma unroll
        for (int s = 0; s < 8; ++s) {
            uint32_t ao = (((2u * (uint32_t)s + atc) ^ ax) << 4);
            uint32_t a0[4], a1[4], b[2];
            ldsm4(a0, abase + ao);
            ldsm4(a1, abase + 4096u + ao);
            ldsm2t(b, bb + (uint32_t)s * 4096u + boH);
            mma16(acc[0], a0, b[0], b[1]);
            mma16(acc[1], a1, b[0], b[1]);
        }
        const int r0 = (w & 1) * 32 + (lane >> 2);
        const int col = (w >> 1) * 8 + 2 * (lane & 3);
        float bb0 = __ldg(qhb + col), bb1 = __ldg(qhb + col + 1);
#pragma unroll
        for (int mi = 0; mi < 2; ++mi)
#pragma unroll
            for (int hh = 0; hh < 2; ++hh) {
                int r = r0 + 16 * mi + 8 * hh;
                float2 v = make_float2(acc[mi][2 * hh] + bb0, acc[mi][2 * hh + 1] + bb1);
                *reinterpret_cast<float2*>(
                    out + (((size_t)b0 + (r >> 5)) * 32 + (r & 31)) * 32 + col) = v;
            }
    }
}

// ---- prep: bake f32 weights into pre-swizzled f16 tile images + pack mask bits ----
__global__ void wprep(const float* __restrict__ enc_w,
                      const float* __restrict__ k1, const float* __restrict__ q1,
                      const float* __restrict__ v1, const float* __restrict__ o1,
                      const float* __restrict__ k2, const float* __restrict__ q2,
                      const float* __restrict__ v2, const float* __restrict__ o2,
                      const float* __restrict__ hw, const float* __restrict__ maskp)
{
    const int m = blockIdx.x, tid = threadIdx.x, w = tid >> 5, lane = tid & 31;
    if (m >= 11) {   // mask packing: one row per thread
        int row = (m - 11) * 256 + tid;
        if (row < 4096 * 32) {
            const float4* mr = reinterpret_cast<const float4*>(maskp + (size_t)row * 32);
            uint32_t bits = 0;
#pragma unroll
            for (int i = 0; i < 8; ++i) {
                float4 v = __ldg(mr + i);
                bits |= ((v.x != 0.f) ? 1u : 0u) << (4 * i);
                bits |= ((v.y != 0.f) ? 1u : 0u) << (4 * i + 1);
                bits |= ((v.z != 0.f) ? 1u : 0u) << (4 * i + 2);
                bits |= ((v.w != 0.f) ? 1u : 0u) << (4 * i + 3);
            }
            g_maskbits[row] = bits;
        }
        return;
    }
    unsigned char* dst = g_wtiles[m];
    const float* srcs[11] = { enc_w, enc_w + 128 * 128, k1, q1, v1, o1, k2, q2, v2, o2, hw };
    const float* src = srcs[m];
    if (m < 10) {
#pragma unroll
        for (int i = 0; i < 16; ++i) {
            int k = 16 * w + i;
            float4 v = __ldg(reinterpret_cast<const float4*>(src + (size_t)k * 128) + lane);
            int n = 4 * lane;
            uint32_t off = (uint32_t)k * 256u + ((((uint32_t)(n >> 3)) ^ (uint32_t)(k & 7)) << 4)
                           + (uint32_t)((n >> 2) & 1) * 8u;
            uint2 val = make_uint2(pack2(v.x, v.y), pack2(v.z, v.w));
            *reinterpret_cast<uint2*>(dst + off) = val;
        }
    } else {
        for (int i = tid; i < 2048; i += 256)
            reinterpret_cast<uint4*>(dst)[i] = make_uint4(0, 0, 0, 0);
        __syncthreads();
#pragma unroll
        for (int it = 0; it < 4; ++it) {
            int k = 16 * w + 4 * it + (lane >> 3);
            int n = 4 * (lane & 7);
            float4 v = __ldg(reinterpret_cast<const float4*>(src + (size_t)k * 32) + (lane & 7));
            uint32_t off = (uint32_t)k * 256u + ((((uint32_t)(n >> 3)) ^ (uint32_t)(k & 7)) << 4)
                           + (uint32_t)((n >> 2) & 1) * 8u;
            uint2 val = make_uint2(pack2(v.x, v.y), pack2(v.z, v.w));
            *reinterpret_cast<uint2*>(dst + off) = val;
        }
    }
}

extern "C" void kernel_launch(void* const* d_in, const int* in_sizes, int n_in,
                              void* d_out, int out_size)
{
    const float* x     = (const float*)d_in[0];
    const float* mask  = (const float*)d_in[1];
    const float* enc_w = (const float*)d_in[2];
    const float* enc_b = (const float*)d_in[3];
    const float* a1_vw = (const float*)d_in[4];
    const float* a1_vb = (const float*)d_in[5];
    const float* a1_kw = (const float*)d_in[6];
    const float* a1_kb = (const float*)d_in[7];
    const float* a1_qw = (const float*)d_in[8];
    const float* a1_qb = (const float*)d_in[9];
    const float* a1_ow = (const float*)d_in[10];
    const float* a1_ob = (const float*)d_in[11];
    const float* a2_vw = (const float*)d_in[12];
    const float* a2_vb = (const float*)d_in[13];
    const float* a2_kw = (const float*)d_in[14];
    const float* a2_kb = (const float*)d_in[15];
    const float* a2_qw = (const float*)d_in[16];
    const float* a2_qb = (const float*)d_in[17];
    const float* a2_ow = (const float*)d_in[18];
    const float* a2_ob = (const float*)d_in[19];
    const float* q_w   = (const float*)d_in[20];
    const float* q_b   = (const float*)d_in[21];

    // 11 weight-tile blocks + 512 mask-pack blocks (4096*32 rows / 256)
    wprep<<<11 + 512, 256>>>(enc_w, a1_kw, a1_qw, a1_vw, a1_ow,
                             a2_kw, a2_qw, a2_vw, a2_ow, q_w, mask);

    cudaFuncSetAttribute(dgn_f16, cudaFuncAttributeMaxDynamicSharedMemorySize, SM_TOTAL);
    dgn_f16<<<2048, 256, SM_TOTAL>>>(
        x, enc_b,
        a1_vb, a1_kb, a1_qb, a1_ob,
        a2_vb, a2_kb, a2_qb, a2_ob,
        q_b, (float*)d_out);
}